// round 11
// baseline (speedup 1.0000x reference)
#include <cuda_runtime.h>
#include <math.h>
#include <cstdint>

#define NROWS 65536
#define DIM   256
#define H1    512
#define H2    2048

// ---------------------------------------------------------------------------
// Device scratch (allocation-free rule)
// ---------------------------------------------------------------------------
__device__ __align__(16) float g_partS[256 * 256];
__device__ __align__(16) float g_partQ[256 * 256];
__device__ __align__(16) float g_scale[DIM];
__device__ __align__(16) float g_shift[DIM];
__device__ __align__(16) float g_w2t[H1 * H2];        // W2^T rounded [512,2048]
__device__ __align__(16) float g_wfr[DIM * H2];       // Wf rounded   [256,2048]
__device__ __align__(16) float g_t2[H2];              // W2@b1 + b2
__device__ __align__(16) float g_beff[DIM];           // Wf@t2 + bf
__device__ __align__(16) float g_t1[DIM * H1];        // T1 = Wf@W2 fp32 (atomic acc)
__device__ __align__(16) float g_weff[DIM * DIM];     // Weff, K-axis pair-permuted
__device__ int g_gcnt;                                // GEMM-block barrier counter
__device__ int g_xcnt;                                // wchain x-scan counter

// ---------------------------------------------------------------------------
// Helpers
// ---------------------------------------------------------------------------
__device__ __forceinline__ unsigned f2tf(float f) {
    unsigned u;
    asm("cvt.rna.tf32.f32 %0, %1;" : "=r"(u) : "f"(f));
    return u;
}
__device__ __forceinline__ float tanh_ap(float x) {
    float r;
    asm("tanh.approx.f32 %0, %1;" : "=f"(r) : "f"(x));
    return r;
}
__device__ __forceinline__ uint32_t smem_u32(const void* p) {
    uint32_t a;
    asm("{ .reg .u64 t; cvta.to.shared.u64 t, %1; cvt.u32.u64 %0, t; }"
        : "=r"(a) : "l"(p));
    return a;
}
__device__ __forceinline__ void cp16(uint32_t dst, const void* src) {
    asm volatile("cp.async.cg.shared.global [%0], [%1], 16;"
                 :: "r"(dst), "l"(src));
}
__device__ __forceinline__ void cp_commit() {
    asm volatile("cp.async.commit_group;" ::: "memory");
}
template <int N>
__device__ __forceinline__ void cp_wait() {
    asm volatile("cp.async.wait_group %0;" :: "n"(N) : "memory");
}

// x-scan helper: one block reduces 256 rows into partial part_id
__device__ __forceinline__ void xscan_block(const float* __restrict__ x,
                                            int part_id, int row0, int tid) {
    __shared__ float4 rs[4][64], rq[4][64];
    int rg = tid >> 6;
    int tc = tid & 63;
    const float4* xp = (const float4*)(x + (size_t)(row0 + rg * 64) * DIM) + tc;
    float4 s = make_float4(0.f, 0.f, 0.f, 0.f);
    float4 q = make_float4(0.f, 0.f, 0.f, 0.f);
#pragma unroll 8
    for (int i = 0; i < 64; i++) {
        float4 v = xp[(size_t)i * 64];
        s.x += v.x; s.y += v.y; s.z += v.z; s.w += v.w;
        q.x += v.x * v.x; q.y += v.y * v.y;
        q.z += v.z * v.z; q.w += v.w * v.w;
    }
    rs[rg][tc] = s; rq[rg][tc] = q;
    __syncthreads();
    if (rg == 0) {
#pragma unroll
        for (int z = 1; z < 4; z++) {
            float4 a = rs[z][tc], b = rq[z][tc];
            s.x += a.x; s.y += a.y; s.z += a.z; s.w += a.w;
            q.x += b.x; q.y += b.y; q.z += b.z; q.w += b.w;
        }
        ((float4*)(g_partS + part_id * 256))[tc] = s;
        ((float4*)(g_partQ + part_id * 256))[tc] = q;
    }
}

// ---------------------------------------------------------------------------
// K0 prep (680 blocks):
//   [0,128)   bn x-scan first half
//   [128,384) W2 transpose + tf32 round -> g_w2t
//   [384,416) round Wf -> g_wfr
//   [416,672) t2 = W2@b1 + b2
//   [672,680) zero g_t1 (+ counter reset)
// ---------------------------------------------------------------------------
__global__ __launch_bounds__(256)
void prep(const float* __restrict__ x, const float* __restrict__ W2,
          const float* __restrict__ Wf, const float* __restrict__ b1,
          const float* __restrict__ b2) {
    __shared__ float ts[64][65];
    int bx = blockIdx.x, tid = threadIdx.x;
    if (bx < 128) {
        xscan_block(x, bx, bx * 256, tid);
    } else if (bx < 384) {
        int b2i = bx - 128;
        int i0 = (b2i & 31) * 64;
        int j0 = (b2i >> 5) * 64;
#pragma unroll
        for (int t = 0; t < 16; t++) {
            int e = tid + t * 256;
            int r = e >> 6, c = e & 63;
            ts[r][c] = W2[(size_t)(i0 + r) * H1 + j0 + c];
        }
        __syncthreads();
#pragma unroll
        for (int t = 0; t < 16; t++) {
            int e = tid + t * 256;
            int r = e >> 6, c = e & 63;
            g_w2t[(size_t)(j0 + r) * H2 + i0 + c] =
                __uint_as_float(f2tf(ts[c][r]));
        }
    } else if (bx < 416) {
        int base = (bx - 384) * 4096;
#pragma unroll
        for (int t = 0; t < 16; t++) {
            int i = base + tid + t * 256;
            float4 v = ((const float4*)Wf)[i];
            v.x = __uint_as_float(f2tf(v.x));
            v.y = __uint_as_float(f2tf(v.y));
            v.z = __uint_as_float(f2tf(v.z));
            v.w = __uint_as_float(f2tf(v.w));
            ((float4*)g_wfr)[i] = v;
        }
    } else if (bx < 672) {
        int w = tid >> 5, lane = tid & 31;
        int row = (bx - 416) * 8 + w;
        const float* wr = W2 + (size_t)row * H1;
        float s = 0.f;
#pragma unroll
        for (int i = 0; i < H1 / 32; i++)
            s += wr[lane + i * 32] * b1[lane + i * 32];
#pragma unroll
        for (int o = 16; o; o >>= 1) s += __shfl_xor_sync(~0u, s, o);
        if (lane == 0) g_t2[row] = s + b2[row];
    } else {
        if (bx == 672 && tid == 0) { g_gcnt = 0; g_xcnt = 0; }
        int base = (bx - 672) * 4096;
        float4 z = make_float4(0.f, 0.f, 0.f, 0.f);
#pragma unroll
        for (int t = 0; t < 16; t++)
            ((float4*)g_t1)[base + tid + t * 256] = z;
    }
}

// ---------------------------------------------------------------------------
// K1 wchain (232 blocks, GEMM_SMEM dyn smem):
//   [0,64)    split-K(16) GEMM T1 += Wf@W2^T -> barrier -> Weff (permuted K)
//   [64,96)   beff = Wf@t2 + bf
//   [96,104)  bn_final (spins on g_xcnt == 128)
//   [104,232) bn x-scan second half (increments g_xcnt)
// ---------------------------------------------------------------------------
#define SMSTRIDE   36
#define ROWBYTES   (SMSTRIDE * 4)
#define A_BYTES    (128 * ROWBYTES)
#define B_BYTES    (256 * ROWBYTES)
#define STAGE_B    (A_BYTES + B_BYTES)
#define STAGES     3
#define GEMM_SMEM  (STAGES * STAGE_B)

__device__ __forceinline__ void issue_tile(const float* aPtr, const float* bPtr,
                                           uint32_t sA, uint32_t sB,
                                           int kOff, int K) {
#pragma unroll
    for (int j = 0; j < 4; j++)
        cp16(sA + j * 32 * ROWBYTES, aPtr + (size_t)j * 32 * K + kOff);
#pragma unroll
    for (int j = 0; j < 8; j++)
        cp16(sB + j * 32 * ROWBYTES, bPtr + (size_t)j * 32 * K + kOff);
}

__global__ __launch_bounds__(256, 1)
void wchain(const float* __restrict__ x, const float* __restrict__ Wf,
            const float* __restrict__ bf, const float* __restrict__ W1,
            const float* __restrict__ gamma, const float* __restrict__ beta) {
    extern __shared__ char smem[];
    const int bx = blockIdx.x;
    const int tid = threadIdx.x;

    if (bx >= 104) {              // ---- bn x-scan, second half ----
        int part = (bx - 104) + 128;
        xscan_block(x, part, part * 256, tid);
        __threadfence();
        __syncthreads();
        if (tid == 0) atomicAdd(&g_xcnt, 1);
        return;
    }
    if (bx >= 96) {               // ---- bn_final: wait for x-scans ----
        if (tid == 0) { while (atomicAdd(&g_xcnt, 0) < 128) {} }
        __syncthreads();
        int c   = (bx - 96) * 32 + (tid >> 3);
        int sub = tid & 7;
        float s = 0.f, q = 0.f;
#pragma unroll 8
        for (int b = sub; b < 256; b += 8) {
            s += g_partS[b * 256 + c];
            q += g_partQ[b * 256 + c];
        }
#pragma unroll
        for (int o = 4; o; o >>= 1) {
            s += __shfl_xor_sync(~0u, s, o);
            q += __shfl_xor_sync(~0u, q, o);
        }
        if (sub == 0) {
            const float inv = 1.0f / (float)NROWS;
            float mu  = s * inv;
            float var = q * inv - mu * mu;
            float sc  = gamma[c] * rsqrtf(var + 1e-5f);
            g_scale[c] = sc;
            g_shift[c] = beta[c] - mu * sc;
        }
        return;
    }
    if (bx >= 64) {               // ---- beff ----
        int w = tid >> 5, lane = tid & 31;
        int row = (bx - 64) * 8 + w;
        const float* wr = Wf + (size_t)row * H2;
        float s = 0.f;
#pragma unroll
        for (int i = 0; i < H2 / 32; i++)
            s += wr[lane + i * 32] * g_t2[lane + i * 32];
#pragma unroll
        for (int o = 16; o; o >>= 1) s += __shfl_xor_sync(~0u, s, o);
        if (lane == 0) g_beff[row] = s + bf[row];
        return;
    }

    // ================= GEMM phase: T1 += Wf @ W2^T (split-K 16) =============
    {
        const uint32_t sbase = smem_u32(smem);
        const int lane = tid & 31;
        const int g    = lane >> 2;
        const int tg   = lane & 3;
        const int wid  = tid >> 5;
        const int wm   = (wid & 1) * 64;
        const int wn   = (wid >> 1) * 64;

        const int xx = bx & 1, yy = (bx >> 1) & 1, z = bx >> 2;
        const int K = H2, kloop = 128, T = kloop >> 5;
        const float* A = g_wfr + z * kloop;
        const float* W = g_w2t + z * kloop;

        const size_t rowBase = (size_t)yy * 128;
        const size_t colBase = (size_t)xx * 256;

        const int r0 = tid >> 3;
        const int c0 = tid & 7;
        const float* aPtr = A + (rowBase + r0) * (size_t)K + c0 * 4;
        const float* bPtr = W + (colBase + r0) * (size_t)K + c0 * 4;
        const uint32_t sAo = r0 * ROWBYTES + c0 * 16;
        const uint32_t sBo = A_BYTES + r0 * ROWBYTES + c0 * 16;

        float acc[4][8][4];
#pragma unroll
        for (int mi = 0; mi < 4; mi++)
#pragma unroll
            for (int ni = 0; ni < 8; ni++)
#pragma unroll
                for (int k = 0; k < 4; k++) acc[mi][ni][k] = 0.f;

        issue_tile(aPtr, bPtr, sbase + sAo, sbase + sBo, 0, K);
        cp_commit();
        issue_tile(aPtr, bPtr, sbase + STAGE_B + sAo, sbase + STAGE_B + sBo, 32, K);
        cp_commit();

        for (int kt = 0; kt < T; kt++) {
            cp_wait<1>();
            __syncthreads();
            if (kt + 2 < T) {
                uint32_t sb2 = sbase + ((kt + 2) % STAGES) * STAGE_B;
                issue_tile(aPtr, bPtr, sb2 + sAo, sb2 + sBo, (kt + 2) * 32, K);
            }
            cp_commit();

            const unsigned* As = (const unsigned*)(smem + (kt % STAGES) * STAGE_B);
            const unsigned* Bs = (const unsigned*)(smem + (kt % STAGES) * STAGE_B + A_BYTES);
#pragma unroll
            for (int kk = 0; kk < 32; kk += 8) {
                unsigned a[4][4], b[8][2];
#pragma unroll
                for (int mi = 0; mi < 4; mi++) {
                    int rr = wm + mi * 16;
                    a[mi][0] = As[(rr + g)     * SMSTRIDE + kk + tg];
                    a[mi][1] = As[(rr + g + 8) * SMSTRIDE + kk + tg];
                    a[mi][2] = As[(rr + g)     * SMSTRIDE + kk + tg + 4];
                    a[mi][3] = As[(rr + g + 8) * SMSTRIDE + kk + tg + 4];
                }
#pragma unroll
                for (int ni = 0; ni < 8; ni++) {
                    int cc = wn + ni * 8 + g;
                    b[ni][0] = Bs[cc * SMSTRIDE + kk + tg];
                    b[ni][1] = Bs[cc * SMSTRIDE + kk + tg + 4];
                }
#pragma unroll
                for (int mi = 0; mi < 4; mi++)
#pragma unroll
                    for (int ni = 0; ni < 8; ni++) {
                        asm volatile(
                            "mma.sync.aligned.m16n8k8.row.col.f32.tf32.tf32.f32 "
                            "{%0,%1,%2,%3}, {%4,%5,%6,%7}, {%8,%9}, {%0,%1,%2,%3};"
                            : "+f"(acc[mi][ni][0]), "+f"(acc[mi][ni][1]),
                              "+f"(acc[mi][ni][2]), "+f"(acc[mi][ni][3])
                            : "r"(a[mi][0]), "r"(a[mi][1]),
                              "r"(a[mi][2]), "r"(a[mi][3]),
                              "r"(b[ni][0]), "r"(b[ni][1]));
                    }
            }
        }

#pragma unroll
        for (int mi = 0; mi < 4; mi++) {
            int row0 = (int)rowBase + wm + mi * 16 + g;
#pragma unroll
            for (int ni = 0; ni < 8; ni++) {
                int col = (int)colBase + wn + ni * 8 + 2 * tg;
                atomicAdd(&g_t1[row0 * H1 + col],           acc[mi][ni][0]);
                atomicAdd(&g_t1[row0 * H1 + col + 1],       acc[mi][ni][1]);
                atomicAdd(&g_t1[(row0 + 8) * H1 + col],     acc[mi][ni][2]);
                atomicAdd(&g_t1[(row0 + 8) * H1 + col + 1], acc[mi][ni][3]);
            }
        }
    }

    // ---- grid barrier among the 64 GEMM blocks ----
    __threadfence();
    __syncthreads();
    if (tid == 0) {
        atomicAdd(&g_gcnt, 1);
        while (atomicAdd(&g_gcnt, 0) < 64) {}
    }
    __syncthreads();

    // ================= Weff phase: Weff = T1 @ W1, stores K-permuted =========
    {
        __shared__ float As2[32][36], Bs2[32][36];
        int i0 = (bx >> 3) * 32, j0 = (bx & 7) * 32;
        int ty = tid >> 4, tx = tid & 15;
        int lr = tid >> 3, lc4 = (tid & 7) * 4;
        float a00 = 0.f, a01 = 0.f, a10 = 0.f, a11 = 0.f;

        float4 ra = *(const float4*)(&g_t1[(i0 + lr) * H1 + lc4]);
        float4 rb = *(const float4*)(&W1[(size_t)lr * DIM + j0 + lc4]);

        for (int kb = 0; kb < H1; kb += 32) {
            *(float4*)(&As2[lr][lc4]) = ra;
            *(float4*)(&Bs2[lr][lc4]) = rb;
            __syncthreads();
            if (kb + 32 < H1) {
                ra = *(const float4*)(&g_t1[(i0 + lr) * H1 + kb + 32 + lc4]);
                rb = *(const float4*)(&W1[(size_t)(kb + 32 + lr) * DIM + j0 + lc4]);
            }
#pragma unroll
            for (int k = 0; k < 32; k++) {
                float x0 = As2[ty * 2][k],     x1 = As2[ty * 2 + 1][k];
                float y0 = Bs2[k][tx * 2],     y1 = Bs2[k][tx * 2 + 1];
                a00 = fmaf(x0, y0, a00); a01 = fmaf(x0, y1, a01);
                a10 = fmaf(x1, y0, a10); a11 = fmaf(x1, y1, a11);
            }
            __syncthreads();
        }
        int r0 = i0 + ty * 2, c0 = j0 + tx * 2, c1 = c0 + 1;
        int p0 = (c0 & ~7) | (2 * (c0 & 3) + ((c0 >> 2) & 1));
        int p1 = (c1 & ~7) | (2 * (c1 & 3) + ((c1 >> 2) & 1));
        g_weff[r0 * DIM + p0]       = __uint_as_float(f2tf(a00));
        g_weff[r0 * DIM + p1]       = __uint_as_float(f2tf(a01));
        g_weff[(r0 + 1) * DIM + p0] = __uint_as_float(f2tf(a10));
        g_weff[(r0 + 1) * DIM + p1] = __uint_as_float(f2tf(a11));
    }
}

// ---------------------------------------------------------------------------
// K2 fused final: 128x128 CTA tile, 128 threads (4 warps of 64x64), 2 CTAs/SM.
// K-axis pair-permuted layout -> LDS.64 fragment loads, stride 40 words
// (conflict-free). A double-buffered (generated in-kernel), B double-buffered
// (cp.async from pre-permuted g_weff). grid (2, 512): col halves.
// ---------------------------------------------------------------------------
#define FSTR     40
#define FROWB    160
#define FA_STAGE (128 * FROWB)         // 20480
#define FB_OFF   (2 * FA_STAGE)
#define F_SMEM   (4 * FA_STAGE)        // 81920

__device__ __forceinline__ void issueB_f(uint32_t sbase, int slot, int kt,
                                         int tid, int colBase) {
#pragma unroll
    for (int j = 0; j < 8; j++) {
        int r = (tid >> 3) + j * 16;
        cp16(sbase + FB_OFF + slot * FA_STAGE + r * FROWB + (tid & 7) * 16,
             g_weff + (colBase + r) * 256 + kt * 32 + (tid & 7) * 4);
    }
}

__global__ __launch_bounds__(128, 2)
void fused_final(const float* __restrict__ x, float* __restrict__ raw,
                 float* __restrict__ out) {
    extern __shared__ char smem[];
    const uint32_t sbase = smem_u32(smem);
    const int tid  = threadIdx.x;
    const int lane = tid & 31;
    const int g    = lane >> 2;
    const int tg   = lane & 3;
    const int wid  = tid >> 5;            // 0..3
    const int wm   = (wid & 1) * 64;
    const int wn   = (wid >> 1) * 64;
    const int colBase = blockIdx.x * 128;
    const bool doRaw  = (blockIdx.x == 0);
    const size_t rowBase = (size_t)blockIdx.y * 128;

    issueB_f(sbase, 0, 0, tid, colBase);
    cp_commit();
    issueB_f(sbase, 1, 1, tid, colBase);
    cp_commit();

    // A-gen geometry: thread covers 8 rows (ar0 + 16j) and the logical column
    // pairs (lc, lc+1) and (lc+4, lc+5); packs them permuted as one uint4 at
    // physical byte offset 16*cf within the row.
    const int cf  = tid & 7;
    const int ar0 = tid >> 3;             // 0..15
    const int lc  = 8 * (cf >> 1) + 2 * (cf & 1);
    const float* xrow = x   + (rowBase + ar0) * 256;
    float*       rrow = raw + (rowBase + ar0) * 256;
    const uint32_t soff = ar0 * FROWB + cf * 16;

    float2 u[8], v[8];
#pragma unroll
    for (int j = 0; j < 8; j++) {
        u[j] = *(const float2*)(xrow + j * 4096 + lc);
        v[j] = *(const float2*)(xrow + j * 4096 + lc + 4);
    }
    {
        float2 scu = *(const float2*)&g_scale[lc];
        float2 scv = *(const float2*)&g_scale[lc + 4];
        float2 shu = *(const float2*)&g_shift[lc];
        float2 shv = *(const float2*)&g_shift[lc + 4];
#pragma unroll
        for (int j = 0; j < 8; j++) {
            float ux = fmaf(u[j].x, scu.x, shu.x);
            float uy = fmaf(u[j].y, scu.y, shu.y);
            float vx = fmaf(v[j].x, scv.x, shv.x);
            float vy = fmaf(v[j].y, scv.y, shv.y);
            if (doRaw) {
                *(float2*)(rrow + j * 4096 + lc) =
                    make_float2(tanh_ap(ux), tanh_ap(uy));
                *(float2*)(rrow + j * 4096 + lc + 4) =
                    make_float2(tanh_ap(vx), tanh_ap(vy));
            }
            uint4 rb;
            rb.x = f2tf(ux); rb.y = f2tf(vx);
            rb.z = f2tf(uy); rb.w = f2tf(vy);
            *(uint4*)(smem + soff + j * 16 * FROWB) = rb;
        }
    }

    float acc[4][8][4];
#pragma unroll
    for (int mi = 0; mi < 4; mi++)
#pragma unroll
        for (int ni = 0; ni < 8; ni++)
#pragma unroll
            for (int k = 0; k < 4; k++) acc[mi][ni][k] = 0.f;

    for (int kt = 0; kt < 8; kt++) {
        if (kt < 7) {
            int off = (kt + 1) * 32 + lc;
#pragma unroll
            for (int j = 0; j < 8; j++) {
                u[j] = *(const float2*)(xrow + j * 4096 + off);
                v[j] = *(const float2*)(xrow + j * 4096 + off + 4);
            }
        }
        cp_wait<1>();
        __syncthreads();

        const unsigned* As = (const unsigned*)(smem + (kt & 1) * FA_STAGE);
        const unsigned* Bs = (const unsigned*)(smem + FB_OFF + (kt & 1) * FA_STAGE);
#pragma unroll
        for (int kk = 0; kk < 32; kk += 8) {
            uint2 a[4][2], b[8];
#pragma unroll
            for (int mi = 0; mi < 4; mi++) {
                int rr = wm + mi * 16;
                a[mi][0] = *(const uint2*)&As[(rr + g)     * FSTR + kk + 2 * tg];
                a[mi][1] = *(const uint2*)&As[(rr + g + 8) * FSTR + kk + 2 * tg];
            }
#pragma unroll
            for (int ni = 0; ni < 8; ni++) {
                int cc = wn + ni * 8 + g;
                b[ni] = *(const uint2*)&Bs[cc * FSTR + kk + 2 * tg];
            }
#pragma unroll
            for (int mi = 0; mi < 4; mi++)
#pragma unroll
                for (int ni = 0; ni < 8; ni++) {
                    asm volatile(
                        "mma.sync.aligned.m16n8k8.row.col.f32.tf32.tf32.f32 "
                        "{%0,%1,%2,%3}, {%4,%5,%6,%7}, {%8,%9}, {%0,%1,%2,%3};"
                        : "+f"(acc[mi][ni][0]), "+f"(acc[mi][ni][1]),
                          "+f"(acc[mi][ni][2]), "+f"(acc[mi][ni][3])
                        : "r"(a[mi][0].x), "r"(a[mi][1].x),
                          "r"(a[mi][0].y), "r"(a[mi][1].y),
                          "r"(b[ni].x), "r"(b[ni].y));
                }
        }

        if (kt < 7) {
            int off = (kt + 1) * 32 + lc;
            float2 scu = *(const float2*)&g_scale[off - lc + lc];   // = g_scale[off]
            scu = *(const float2*)&g_scale[off];
            float2 scv = *(const float2*)&g_scale[off + 4];
            float2 shu = *(const float2*)&g_shift[off];
            float2 shv = *(const float2*)&g_shift[off + 4];
            char* dst = smem + ((kt + 1) & 1) * FA_STAGE + soff;
#pragma unroll
            for (int j = 0; j < 8; j++) {
                float ux = fmaf(u[j].x, scu.x, shu.x);
                float uy = fmaf(u[j].y, scu.y, shu.y);
                float vx = fmaf(v[j].x, scv.x, shv.x);
                float vy = fmaf(v[j].y, scv.y, shv.y);
                if (doRaw) {
                    *(float2*)(rrow + j * 4096 + off) =
                        make_float2(tanh_ap(ux), tanh_ap(uy));
                    *(float2*)(rrow + j * 4096 + off + 4) =
                        make_float2(tanh_ap(vx), tanh_ap(vy));
                }
                uint4 rb;
                rb.x = f2tf(ux); rb.y = f2tf(vx);
                rb.z = f2tf(uy); rb.w = f2tf(vy);
                *(uint4*)(dst + j * 16 * FROWB) = rb;
            }
        }
        __syncthreads();
        if (kt + 2 < 8) issueB_f(sbase, kt & 1, kt + 2, tid, colBase);
        cp_commit();
    }

    // epilogue: + beff, tanh, store (logical n columns; beff unpermuted)
#pragma unroll
    for (int mi = 0; mi < 4; mi++) {
        size_t row0 = rowBase + wm + mi * 16 + g;
#pragma unroll
        for (int ni = 0; ni < 8; ni++) {
            int col = colBase + wn + ni * 8 + 2 * tg;
            float v0 = tanh_ap(acc[mi][ni][0] + g_beff[col]);
            float v1 = tanh_ap(acc[mi][ni][1] + g_beff[col + 1]);
            float v2 = tanh_ap(acc[mi][ni][2] + g_beff[col]);
            float v3 = tanh_ap(acc[mi][ni][3] + g_beff[col + 1]);
            *(float2*)&out[row0 * 256 + col]       = make_float2(v0, v1);
            *(float2*)&out[(row0 + 8) * 256 + col] = make_float2(v2, v3);
        }
    }
}

// ---------------------------------------------------------------------------
// Launch (3 kernels)
// ---------------------------------------------------------------------------
extern "C" void kernel_launch(void* const* d_in, const int* in_sizes, int n_in,
                              void* d_out, int out_size) {
    const float* x     = (const float*)d_in[0];
    const float* gamma = (const float*)d_in[1];
    const float* beta  = (const float*)d_in[2];
    const float* W1    = (const float*)d_in[3];
    const float* b1    = (const float*)d_in[4];
    const float* W2    = (const float*)d_in[5];
    const float* b2    = (const float*)d_in[6];
    const float* Wf    = (const float*)d_in[7];
    const float* bf    = (const float*)d_in[8];

    float* out = (float*)d_out;
    float* raw = out + (size_t)NROWS * DIM;

    cudaFuncSetAttribute(wchain,
                         cudaFuncAttributeMaxDynamicSharedMemorySize, GEMM_SMEM);
    cudaFuncSetAttribute(fused_final,
                         cudaFuncAttributeMaxDynamicSharedMemorySize, F_SMEM);

    prep<<<680, 256>>>(x, W2, Wf, b1, b2);
    wchain<<<232, 256, GEMM_SMEM>>>(x, Wf, bf, W1, gamma, beta);
    fused_final<<<dim3(2, NROWS / 128), 128, F_SMEM>>>(x, raw, out);
}

// round 12
// speedup vs baseline: 1.0289x; 1.0289x over previous
#include <cuda_runtime.h>
#include <math.h>
#include <cstdint>

#define NROWS 65536
#define DIM   256
#define H1    512
#define H2    2048

// ---------------------------------------------------------------------------
// Device scratch (allocation-free rule)
// ---------------------------------------------------------------------------
__device__ __align__(16) float g_partS[256 * 256];
__device__ __align__(16) float g_partQ[256 * 256];
__device__ __align__(16) float g_scale[DIM];
__device__ __align__(16) float g_shift[DIM];
__device__ __align__(16) float g_w2t[H1 * H2];        // W2^T rounded [512,2048]
__device__ __align__(16) float g_wfr[DIM * H2];       // Wf rounded   [256,2048]
__device__ __align__(16) float g_t2[H2];              // W2@b1 + b2
__device__ __align__(16) float g_beff[DIM];           // Wf@t2 + bf
__device__ __align__(16) float g_t1[DIM * H1];        // T1 = Wf@W2 fp32 (atomic acc)
__device__ __align__(16) float g_weff[DIM * DIM];     // Weff, K-axis pair-permuted

// ---------------------------------------------------------------------------
// Helpers
// ---------------------------------------------------------------------------
__device__ __forceinline__ unsigned f2tf(float f) {
    unsigned u;
    asm("cvt.rna.tf32.f32 %0, %1;" : "=r"(u) : "f"(f));
    return u;
}
__device__ __forceinline__ float tanh_ap(float x) {
    float r;
    asm("tanh.approx.f32 %0, %1;" : "=f"(r) : "f"(x));
    return r;
}
__device__ __forceinline__ uint32_t smem_u32(const void* p) {
    uint32_t a;
    asm("{ .reg .u64 t; cvta.to.shared.u64 t, %1; cvt.u32.u64 %0, t; }"
        : "=r"(a) : "l"(p));
    return a;
}
__device__ __forceinline__ void cp16(uint32_t dst, const void* src) {
    asm volatile("cp.async.cg.shared.global [%0], [%1], 16;"
                 :: "r"(dst), "l"(src));
}
__device__ __forceinline__ void cp_commit() {
    asm volatile("cp.async.commit_group;" ::: "memory");
}
template <int N>
__device__ __forceinline__ void cp_wait() {
    asm volatile("cp.async.wait_group %0;" :: "n"(N) : "memory");
}

// x-scan helper: one block reduces 256 rows into partial part_id
__device__ __forceinline__ void xscan_block(const float* __restrict__ x,
                                            int part_id, int row0, int tid) {
    __shared__ float4 rs[4][64], rq[4][64];
    int rg = tid >> 6;
    int tc = tid & 63;
    const float4* xp = (const float4*)(x + (size_t)(row0 + rg * 64) * DIM) + tc;
    float4 s = make_float4(0.f, 0.f, 0.f, 0.f);
    float4 q = make_float4(0.f, 0.f, 0.f, 0.f);
#pragma unroll 8
    for (int i = 0; i < 64; i++) {
        float4 v = xp[(size_t)i * 64];
        s.x += v.x; s.y += v.y; s.z += v.z; s.w += v.w;
        q.x += v.x * v.x; q.y += v.y * v.y;
        q.z += v.z * v.z; q.w += v.w * v.w;
    }
    rs[rg][tc] = s; rq[rg][tc] = q;
    __syncthreads();
    if (rg == 0) {
#pragma unroll
        for (int z = 1; z < 4; z++) {
            float4 a = rs[z][tc], b = rq[z][tc];
            s.x += a.x; s.y += a.y; s.z += a.z; s.w += a.w;
            q.x += b.x; q.y += b.y; q.z += b.z; q.w += b.w;
        }
        ((float4*)(g_partS + part_id * 256))[tc] = s;
        ((float4*)(g_partQ + part_id * 256))[tc] = q;
    }
}

// ---------------------------------------------------------------------------
// K0 prep (680 blocks):
//   [0,128)   bn x-scan first half (rows 0..32767)
//   [128,384) W2 transpose + tf32 round -> g_w2t
//   [384,416) round Wf -> g_wfr
//   [416,672) t2 = W2@b1 + b2
//   [672,680) zero g_t1
// ---------------------------------------------------------------------------
__global__ __launch_bounds__(256)
void prep(const float* __restrict__ x, const float* __restrict__ W2,
          const float* __restrict__ Wf, const float* __restrict__ b1,
          const float* __restrict__ b2) {
    __shared__ float ts[64][65];
    int bx = blockIdx.x, tid = threadIdx.x;
    if (bx < 128) {
        xscan_block(x, bx, bx * 256, tid);
    } else if (bx < 384) {
        int b2i = bx - 128;
        int i0 = (b2i & 31) * 64;
        int j0 = (b2i >> 5) * 64;
#pragma unroll
        for (int t = 0; t < 16; t++) {
            int e = tid + t * 256;
            int r = e >> 6, c = e & 63;
            ts[r][c] = W2[(size_t)(i0 + r) * H1 + j0 + c];
        }
        __syncthreads();
#pragma unroll
        for (int t = 0; t < 16; t++) {
            int e = tid + t * 256;
            int r = e >> 6, c = e & 63;
            g_w2t[(size_t)(j0 + r) * H2 + i0 + c] =
                __uint_as_float(f2tf(ts[c][r]));
        }
    } else if (bx < 416) {
        int base = (bx - 384) * 4096;
#pragma unroll
        for (int t = 0; t < 16; t++) {
            int i = base + tid + t * 256;
            float4 v = ((const float4*)Wf)[i];
            v.x = __uint_as_float(f2tf(v.x));
            v.y = __uint_as_float(f2tf(v.y));
            v.z = __uint_as_float(f2tf(v.z));
            v.w = __uint_as_float(f2tf(v.w));
            ((float4*)g_wfr)[i] = v;
        }
    } else if (bx < 672) {
        int w = tid >> 5, lane = tid & 31;
        int row = (bx - 416) * 8 + w;
        const float* wr = W2 + (size_t)row * H1;
        float s = 0.f;
#pragma unroll
        for (int i = 0; i < H1 / 32; i++)
            s += wr[lane + i * 32] * b1[lane + i * 32];
#pragma unroll
        for (int o = 16; o; o >>= 1) s += __shfl_xor_sync(~0u, s, o);
        if (lane == 0) g_t2[row] = s + b2[row];
    } else {
        int base = (bx - 672) * 4096;
        float4 z = make_float4(0.f, 0.f, 0.f, 0.f);
#pragma unroll
        for (int t = 0; t < 16; t++)
            ((float4*)g_t1)[base + tid + t * 256] = z;
    }
}

// ---------------------------------------------------------------------------
// K1 wchain (224 blocks, GEMM_SMEM dyn smem):
//   [0,64)   split-K(16) tf32 GEMM: T1 += Wf @ W2^T  (atomicAdd epilogue)
//   [64,96)  beff = Wf@t2 + bf
//   [96,224) bn x-scan second half (rows 32768..65535)
// ---------------------------------------------------------------------------
#define SMSTRIDE   36
#define ROWBYTES   (SMSTRIDE * 4)
#define A_BYTES    (128 * ROWBYTES)
#define B_BYTES    (256 * ROWBYTES)
#define STAGE_B    (A_BYTES + B_BYTES)
#define STAGES     3
#define GEMM_SMEM  (STAGES * STAGE_B)

__device__ __forceinline__ void issue_tile(const float* aPtr, const float* bPtr,
                                           uint32_t sA, uint32_t sB,
                                           int kOff, int K) {
#pragma unroll
    for (int j = 0; j < 4; j++)
        cp16(sA + j * 32 * ROWBYTES, aPtr + (size_t)j * 32 * K + kOff);
#pragma unroll
    for (int j = 0; j < 8; j++)
        cp16(sB + j * 32 * ROWBYTES, bPtr + (size_t)j * 32 * K + kOff);
}

__global__ __launch_bounds__(256, 1)
void wchain(const float* __restrict__ x, const float* __restrict__ Wf,
            const float* __restrict__ bf) {
    extern __shared__ char smem[];
    const int bx = blockIdx.x;
    const int tid = threadIdx.x;

    if (bx >= 96) {               // ---- bn x-scan, second half ----
        int part = (bx - 96) + 128;
        xscan_block(x, part, part * 256, tid);
        return;
    }
    if (bx >= 64) {               // ---- beff ----
        int w = tid >> 5, lane = tid & 31;
        int row = (bx - 64) * 8 + w;
        const float* wr = Wf + (size_t)row * H2;
        float s = 0.f;
#pragma unroll
        for (int i = 0; i < H2 / 32; i++)
            s += wr[lane + i * 32] * g_t2[lane + i * 32];
#pragma unroll
        for (int o = 16; o; o >>= 1) s += __shfl_xor_sync(~0u, s, o);
        if (lane == 0) g_beff[row] = s + bf[row];
        return;
    }

    // ---- split-K(16) GEMM: A=g_wfr [256,2048], W=g_w2t [512,2048], slice 128 ----
    const uint32_t sbase = smem_u32(smem);
    const int lane = tid & 31;
    const int g    = lane >> 2;
    const int tg   = lane & 3;
    const int wid  = tid >> 5;
    const int wm   = (wid & 1) * 64;
    const int wn   = (wid >> 1) * 64;

    const int xx = bx & 1, yy = (bx >> 1) & 1, z = bx >> 2;   // z: 0..15
    const int K = H2, kloop = 128, T = kloop >> 5;            // T = 4
    const float* A = g_wfr + z * kloop;
    const float* W = g_w2t + z * kloop;

    const size_t rowBase = (size_t)yy * 128;
    const size_t colBase = (size_t)xx * 256;

    const int r0 = tid >> 3;
    const int c0 = tid & 7;
    const float* aPtr = A + (rowBase + r0) * (size_t)K + c0 * 4;
    const float* bPtr = W + (colBase + r0) * (size_t)K + c0 * 4;
    const uint32_t sAo = r0 * ROWBYTES + c0 * 16;
    const uint32_t sBo = A_BYTES + r0 * ROWBYTES + c0 * 16;

    float acc[4][8][4];
#pragma unroll
    for (int mi = 0; mi < 4; mi++)
#pragma unroll
        for (int ni = 0; ni < 8; ni++)
#pragma unroll
            for (int k = 0; k < 4; k++) acc[mi][ni][k] = 0.f;

    issue_tile(aPtr, bPtr, sbase + sAo, sbase + sBo, 0, K);
    cp_commit();
    issue_tile(aPtr, bPtr, sbase + STAGE_B + sAo, sbase + STAGE_B + sBo, 32, K);
    cp_commit();

    for (int kt = 0; kt < T; kt++) {
        cp_wait<1>();
        __syncthreads();
        if (kt + 2 < T) {
            uint32_t sb2 = sbase + ((kt + 2) % STAGES) * STAGE_B;
            issue_tile(aPtr, bPtr, sb2 + sAo, sb2 + sBo, (kt + 2) * 32, K);
        }
        cp_commit();

        const unsigned* As = (const unsigned*)(smem + (kt % STAGES) * STAGE_B);
        const unsigned* Bs = (const unsigned*)(smem + (kt % STAGES) * STAGE_B + A_BYTES);
#pragma unroll
        for (int kk = 0; kk < 32; kk += 8) {
            unsigned a[4][4], b[8][2];
#pragma unroll
            for (int mi = 0; mi < 4; mi++) {
                int rr = wm + mi * 16;
                a[mi][0] = As[(rr + g)     * SMSTRIDE + kk + tg];
                a[mi][1] = As[(rr + g + 8) * SMSTRIDE + kk + tg];
                a[mi][2] = As[(rr + g)     * SMSTRIDE + kk + tg + 4];
                a[mi][3] = As[(rr + g + 8) * SMSTRIDE + kk + tg + 4];
            }
#pragma unroll
            for (int ni = 0; ni < 8; ni++) {
                int cc = wn + ni * 8 + g;
                b[ni][0] = Bs[cc * SMSTRIDE + kk + tg];
                b[ni][1] = Bs[cc * SMSTRIDE + kk + tg + 4];
            }
#pragma unroll
            for (int mi = 0; mi < 4; mi++)
#pragma unroll
                for (int ni = 0; ni < 8; ni++) {
                    asm volatile(
                        "mma.sync.aligned.m16n8k8.row.col.f32.tf32.tf32.f32 "
                        "{%0,%1,%2,%3}, {%4,%5,%6,%7}, {%8,%9}, {%0,%1,%2,%3};"
                        : "+f"(acc[mi][ni][0]), "+f"(acc[mi][ni][1]),
                          "+f"(acc[mi][ni][2]), "+f"(acc[mi][ni][3])
                        : "r"(a[mi][0]), "r"(a[mi][1]),
                          "r"(a[mi][2]), "r"(a[mi][3]),
                          "r"(b[ni][0]), "r"(b[ni][1]));
                }
        }
    }

#pragma unroll
    for (int mi = 0; mi < 4; mi++) {
        int row0 = (int)rowBase + wm + mi * 16 + g;
#pragma unroll
        for (int ni = 0; ni < 8; ni++) {
            int col = (int)colBase + wn + ni * 8 + 2 * tg;
            atomicAdd(&g_t1[row0 * H1 + col],           acc[mi][ni][0]);
            atomicAdd(&g_t1[row0 * H1 + col + 1],       acc[mi][ni][1]);
            atomicAdd(&g_t1[(row0 + 8) * H1 + col],     acc[mi][ni][2]);
            atomicAdd(&g_t1[(row0 + 8) * H1 + col + 1], acc[mi][ni][3]);
        }
    }
}

// ---------------------------------------------------------------------------
// K2 weff_k (72 blocks):
//   [0,64)  Weff = T1 @ W1 (fp32 FFMA 32x32 tiles) + round, stores K-PERMUTED
//   [64,72) bn_final
// ---------------------------------------------------------------------------
__global__ __launch_bounds__(256)
void weff_k(const float* __restrict__ W1, const float* __restrict__ gamma,
            const float* __restrict__ beta) {
    int tid = threadIdx.x;
    if (blockIdx.x >= 64) {
        int c   = (blockIdx.x - 64) * 32 + (tid >> 3);
        int sub = tid & 7;
        float s = 0.f, q = 0.f;
#pragma unroll 8
        for (int b = sub; b < 256; b += 8) {
            s += g_partS[b * 256 + c];
            q += g_partQ[b * 256 + c];
        }
#pragma unroll
        for (int o = 4; o; o >>= 1) {
            s += __shfl_xor_sync(~0u, s, o);
            q += __shfl_xor_sync(~0u, q, o);
        }
        if (sub == 0) {
            const float inv = 1.0f / (float)NROWS;
            float mu  = s * inv;
            float var = q * inv - mu * mu;
            float sc  = gamma[c] * rsqrtf(var + 1e-5f);
            g_scale[c] = sc;
            g_shift[c] = beta[c] - mu * sc;
        }
        return;
    }
    __shared__ float As[32][36], Bs[32][36];
    int i0 = (blockIdx.x >> 3) * 32, j0 = (blockIdx.x & 7) * 32;
    int ty = tid >> 4, tx = tid & 15;
    int lr = tid >> 3, lc4 = (tid & 7) * 4;
    float a00 = 0.f, a01 = 0.f, a10 = 0.f, a11 = 0.f;

    float4 ra = *(const float4*)(&g_t1[(i0 + lr) * H1 + lc4]);
    float4 rb = *(const float4*)(&W1[(size_t)lr * DIM + j0 + lc4]);

    for (int kb = 0; kb < H1; kb += 32) {
        *(float4*)(&As[lr][lc4]) = ra;
        *(float4*)(&Bs[lr][lc4]) = rb;
        __syncthreads();
        if (kb + 32 < H1) {
            ra = *(const float4*)(&g_t1[(i0 + lr) * H1 + kb + 32 + lc4]);
            rb = *(const float4*)(&W1[(size_t)(kb + 32 + lr) * DIM + j0 + lc4]);
        }
#pragma unroll
        for (int k = 0; k < 32; k++) {
            float x0 = As[ty * 2][k],     x1 = As[ty * 2 + 1][k];
            float y0 = Bs[k][tx * 2],     y1 = Bs[k][tx * 2 + 1];
            a00 = fmaf(x0, y0, a00); a01 = fmaf(x0, y1, a01);
            a10 = fmaf(x1, y0, a10); a11 = fmaf(x1, y1, a11);
        }
        __syncthreads();
    }
    // store with K-axis pair permutation: within each 8-group,
    // logical col c -> physical 2*(c&3) + ((c>>2)&1)
    int r0 = i0 + ty * 2, c0 = j0 + tx * 2, c1 = c0 + 1;
    int p0 = (c0 & ~7) | (2 * (c0 & 3) + ((c0 >> 2) & 1));
    int p1 = (c1 & ~7) | (2 * (c1 & 3) + ((c1 >> 2) & 1));
    g_weff[r0 * DIM + p0]       = __uint_as_float(f2tf(a00));
    g_weff[r0 * DIM + p1]       = __uint_as_float(f2tf(a01));
    g_weff[(r0 + 1) * DIM + p0] = __uint_as_float(f2tf(a10));
    g_weff[(r0 + 1) * DIM + p1] = __uint_as_float(f2tf(a11));
}

// ---------------------------------------------------------------------------
// K3 fused final: 128x128 CTA tile, 128 threads (4 warps of 64x64), 2 CTAs/SM.
// K-axis pair-permuted layout -> LDS.64 fragment loads, stride 40 words
// (conflict-free, verified). A double-buffered (generated in-kernel),
// B double-buffered (cp.async from pre-permuted g_weff).
// ---------------------------------------------------------------------------
#define FSTR     40
#define FROWB    160
#define FA_STAGE (128 * FROWB)         // 20480
#define FB_OFF   (2 * FA_STAGE)
#define F_SMEM   (4 * FA_STAGE)        // 81920

__device__ __forceinline__ void issueB_f(uint32_t sbase, int slot, int kt,
                                         int tid, int colBase) {
#pragma unroll
    for (int j = 0; j < 8; j++) {
        int r = (tid >> 3) + j * 16;
        cp16(sbase + FB_OFF + slot * FA_STAGE + r * FROWB + (tid & 7) * 16,
             g_weff + (colBase + r) * 256 + kt * 32 + (tid & 7) * 4);
    }
}

__global__ __launch_bounds__(128, 2)
void fused_final(const float* __restrict__ x, float* __restrict__ raw,
                 float* __restrict__ out) {
    extern __shared__ char smem[];
    const uint32_t sbase = smem_u32(smem);
    const int tid  = threadIdx.x;
    const int lane = tid & 31;
    const int g    = lane >> 2;
    const int tg   = lane & 3;
    const int wid  = tid >> 5;            // 0..3
    const int wm   = (wid & 1) * 64;
    const int wn   = (wid >> 1) * 64;
    const int colBase = blockIdx.x * 128;
    const bool doRaw  = (blockIdx.x == 0);
    const size_t rowBase = (size_t)blockIdx.y * 128;

    issueB_f(sbase, 0, 0, tid, colBase);
    cp_commit();
    issueB_f(sbase, 1, 1, tid, colBase);
    cp_commit();

    // A-gen: thread covers 8 rows (ar0 + 16j); packs logical col pairs
    // (lc,lc+1) and (lc+4,lc+5) as one permuted uint4 at byte offset 16*cf.
    const int cf  = tid & 7;
    const int ar0 = tid >> 3;             // 0..15
    const int lc  = 8 * (cf >> 1) + 2 * (cf & 1);
    const float* xrow = x   + (rowBase + ar0) * 256;
    float*       rrow = raw + (rowBase + ar0) * 256;
    const uint32_t soff = ar0 * FROWB + cf * 16;

    float2 u[8], v[8];
#pragma unroll
    for (int j = 0; j < 8; j++) {
        u[j] = *(const float2*)(xrow + j * 4096 + lc);
        v[j] = *(const float2*)(xrow + j * 4096 + lc + 4);
    }
    {
        float2 scu = *(const float2*)&g_scale[lc];
        float2 scv = *(const float2*)&g_scale[lc + 4];
        float2 shu = *(const float2*)&g_shift[lc];
        float2 shv = *(const float2*)&g_shift[lc + 4];
#pragma unroll
        for (int j = 0; j < 8; j++) {
            float ux = fmaf(u[j].x, scu.x, shu.x);
            float uy = fmaf(u[j].y, scu.y, shu.y);
            float vx = fmaf(v[j].x, scv.x, shv.x);
            float vy = fmaf(v[j].y, scv.y, shv.y);
            if (doRaw) {
                *(float2*)(rrow + j * 4096 + lc) =
                    make_float2(tanh_ap(ux), tanh_ap(uy));
                *(float2*)(rrow + j * 4096 + lc + 4) =
                    make_float2(tanh_ap(vx), tanh_ap(vy));
            }
            uint4 rb;
            rb.x = f2tf(ux); rb.y = f2tf(vx);
            rb.z = f2tf(uy); rb.w = f2tf(vy);
            *(uint4*)(smem + soff + j * 16 * FROWB) = rb;
        }
    }

    float acc[4][8][4];
#pragma unroll
    for (int mi = 0; mi < 4; mi++)
#pragma unroll
        for (int ni = 0; ni < 8; ni++)
#pragma unroll
            for (int k = 0; k < 4; k++) acc[mi][ni][k] = 0.f;

    for (int kt = 0; kt < 8; kt++) {
        if (kt < 7) {
            int off = (kt + 1) * 32 + lc;
#pragma unroll
            for (int j = 0; j < 8; j++) {
                u[j] = *(const float2*)(xrow + j * 4096 + off);
                v[j] = *(const float2*)(xrow + j * 4096 + off + 4);
            }
        }
        cp_wait<1>();
        __syncthreads();

        const unsigned* As = (const unsigned*)(smem + (kt & 1) * FA_STAGE);
        const unsigned* Bs = (const unsigned*)(smem + FB_OFF + (kt & 1) * FA_STAGE);
#pragma unroll
        for (int kk = 0; kk < 32; kk += 8) {
            uint2 a[4][2], b[8];
#pragma unroll
            for (int mi = 0; mi < 4; mi++) {
                int rr = wm + mi * 16;
                a[mi][0] = *(const uint2*)&As[(rr + g)     * FSTR + kk + 2 * tg];
                a[mi][1] = *(const uint2*)&As[(rr + g + 8) * FSTR + kk + 2 * tg];
            }
#pragma unroll
            for (int ni = 0; ni < 8; ni++) {
                int cc = wn + ni * 8 + g;
                b[ni] = *(const uint2*)&Bs[cc * FSTR + kk + 2 * tg];
            }
#pragma unroll
            for (int mi = 0; mi < 4; mi++)
#pragma unroll
                for (int ni = 0; ni < 8; ni++) {
                    asm volatile(
                        "mma.sync.aligned.m16n8k8.row.col.f32.tf32.tf32.f32 "
                        "{%0,%1,%2,%3}, {%4,%5,%6,%7}, {%8,%9}, {%0,%1,%2,%3};"
                        : "+f"(acc[mi][ni][0]), "+f"(acc[mi][ni][1]),
                          "+f"(acc[mi][ni][2]), "+f"(acc[mi][ni][3])
                        : "r"(a[mi][0].x), "r"(a[mi][1].x),
                          "r"(a[mi][0].y), "r"(a[mi][1].y),
                          "r"(b[ni].x), "r"(b[ni].y));
                }
        }

        if (kt < 7) {
            int off = (kt + 1) * 32 + lc;
            float2 scu = *(const float2*)&g_scale[off];
            float2 scv = *(const float2*)&g_scale[off + 4];
            float2 shu = *(const float2*)&g_shift[off];
            float2 shv = *(const float2*)&g_shift[off + 4];
            char* dst = smem + ((kt + 1) & 1) * FA_STAGE + soff;
#pragma unroll
            for (int j = 0; j < 8; j++) {
                float ux = fmaf(u[j].x, scu.x, shu.x);
                float uy = fmaf(u[j].y, scu.y, shu.y);
                float vx = fmaf(v[j].x, scv.x, shv.x);
                float vy = fmaf(v[j].y, scv.y, shv.y);
                if (doRaw) {
                    *(float2*)(rrow + j * 4096 + off) =
                        make_float2(tanh_ap(ux), tanh_ap(uy));
                    *(float2*)(rrow + j * 4096 + off + 4) =
                        make_float2(tanh_ap(vx), tanh_ap(vy));
                }
                uint4 rb;
                rb.x = f2tf(ux); rb.y = f2tf(vx);
                rb.z = f2tf(uy); rb.w = f2tf(vy);
                *(uint4*)(dst + j * 16 * FROWB) = rb;
            }
        }
        __syncthreads();
        if (kt + 2 < 8) issueB_f(sbase, kt & 1, kt + 2, tid, colBase);
        cp_commit();
    }

    // epilogue: + beff, tanh, store (logical n columns; beff unpermuted)
#pragma unroll
    for (int mi = 0; mi < 4; mi++) {
        size_t row0 = rowBase + wm + mi * 16 + g;
#pragma unroll
        for (int ni = 0; ni < 8; ni++) {
            int col = colBase + wn + ni * 8 + 2 * tg;
            float v0 = tanh_ap(acc[mi][ni][0] + g_beff[col]);
            float v1 = tanh_ap(acc[mi][ni][1] + g_beff[col + 1]);
            float v2 = tanh_ap(acc[mi][ni][2] + g_beff[col]);
            float v3 = tanh_ap(acc[mi][ni][3] + g_beff[col + 1]);
            *(float2*)&out[row0 * 256 + col]       = make_float2(v0, v1);
            *(float2*)&out[(row0 + 8) * 256 + col] = make_float2(v2, v3);
        }
    }
}

// ---------------------------------------------------------------------------
// Launch (4 kernels)
// ---------------------------------------------------------------------------
extern "C" void kernel_launch(void* const* d_in, const int* in_sizes, int n_in,
                              void* d_out, int out_size) {
    const float* x     = (const float*)d_in[0];
    const float* gamma = (const float*)d_in[1];
    const float* beta  = (const float*)d_in[2];
    const float* W1    = (const float*)d_in[3];
    const float* b1    = (const float*)d_in[4];
    const float* W2    = (const float*)d_in[5];
    const float* b2    = (const float*)d_in[6];
    const float* Wf    = (const float*)d_in[7];
    const float* bf    = (const float*)d_in[8];

    float* out = (float*)d_out;
    float* raw = out + (size_t)NROWS * DIM;

    cudaFuncSetAttribute(wchain,
                         cudaFuncAttributeMaxDynamicSharedMemorySize, GEMM_SMEM);
    cudaFuncSetAttribute(fused_final,
                         cudaFuncAttributeMaxDynamicSharedMemorySize, F_SMEM);

    prep<<<680, 256>>>(x, W2, Wf, b1, b2);
    wchain<<<224, 256, GEMM_SMEM>>>(x, Wf, bf);
    weff_k<<<72, 256>>>(W1, gamma, beta);
    fused_final<<<dim3(2, NROWS / 128), 128, F_SMEM>>>(x, raw, out);
}

// round 13
// speedup vs baseline: 1.1351x; 1.1033x over previous
#include <cuda_runtime.h>
#include <math.h>
#include <cstdint>

#define NROWS 65536
#define DIM   256
#define H1    512
#define H2    2048
#define NPART 512

// ---------------------------------------------------------------------------
// Device scratch (allocation-free rule)
// ---------------------------------------------------------------------------
__device__ __align__(16) float g_partS[NPART * 256];
__device__ __align__(16) float g_partQ[NPART * 256];
__device__ __align__(16) float g_scale[DIM];
__device__ __align__(16) float g_shift[DIM];
__device__ __align__(16) float g_w2t[H1 * H2];        // W2^T rounded [512,2048]
__device__ __align__(16) float g_wfr[DIM * H2];       // Wf rounded   [256,2048]
__device__ __align__(16) float g_t2[H2];              // W2@b1 + b2
__device__ __align__(16) float g_beff[DIM];           // Wf@t2 + bf
__device__ __align__(16) float g_t1[DIM * H1];        // T1 = Wf@W2 fp32 (atomic acc)
__device__ __align__(16) float g_weff[DIM * DIM];     // Wf@W2@W1 rounded [256,256]

// ---------------------------------------------------------------------------
// Helpers
// ---------------------------------------------------------------------------
__device__ __forceinline__ unsigned f2tf(float f) {
    unsigned u;
    asm("cvt.rna.tf32.f32 %0, %1;" : "=r"(u) : "f"(f));
    return u;
}
__device__ __forceinline__ float tanh_ap(float x) {
    float r;
    asm("tanh.approx.f32 %0, %1;" : "=f"(r) : "f"(x));
    return r;
}
__device__ __forceinline__ uint32_t smem_u32(const void* p) {
    uint32_t a;
    asm("{ .reg .u64 t; cvta.to.shared.u64 t, %1; cvt.u32.u64 %0, t; }"
        : "=r"(a) : "l"(p));
    return a;
}
__device__ __forceinline__ void cp16(uint32_t dst, const void* src) {
    asm volatile("cp.async.cg.shared.global [%0], [%1], 16;"
                 :: "r"(dst), "l"(src));
}
__device__ __forceinline__ void cp_commit() {
    asm volatile("cp.async.commit_group;" ::: "memory");
}
template <int N>
__device__ __forceinline__ void cp_wait() {
    asm volatile("cp.async.wait_group %0;" :: "n"(N) : "memory");
}

// x-scan helper: one block reduces 128 rows starting at row0 into partial id
__device__ __forceinline__ void xscan_block(const float* __restrict__ x,
                                            int part_id, int row0, int tid) {
    __shared__ float4 rs[4][64], rq[4][64];
    int rg = tid >> 6;                 // 0..3 row groups (32 rows each)
    int tc = tid & 63;                 // float4 column
    const float4* xp = (const float4*)(x + (size_t)(row0 + rg * 32) * DIM) + tc;
    float4 s = make_float4(0.f, 0.f, 0.f, 0.f);
    float4 q = make_float4(0.f, 0.f, 0.f, 0.f);
#pragma unroll 8
    for (int i = 0; i < 32; i++) {
        float4 v = xp[(size_t)i * 64];
        s.x += v.x; s.y += v.y; s.z += v.z; s.w += v.w;
        q.x += v.x * v.x; q.y += v.y * v.y;
        q.z += v.z * v.z; q.w += v.w * v.w;
    }
    rs[rg][tc] = s; rq[rg][tc] = q;
    __syncthreads();
    if (rg == 0) {
#pragma unroll
        for (int z = 1; z < 4; z++) {
            float4 a = rs[z][tc], b = rq[z][tc];
            s.x += a.x; s.y += a.y; s.z += a.z; s.w += a.w;
            q.x += b.x; q.y += b.y; q.z += b.z; q.w += b.w;
        }
        ((float4*)(g_partS + part_id * 256))[tc] = s;
        ((float4*)(g_partQ + part_id * 256))[tc] = q;
    }
}

// ---------------------------------------------------------------------------
// K0 prep (808 blocks):
//   [0,256)   bn x-scan first half (rows 0..32767, 128 rows/block)
//   [256,512) W2 transpose + tf32 round -> g_w2t
//   [512,544) round Wf -> g_wfr
//   [544,800) t2 = W2@b1 + b2
//   [800,808) zero g_t1
// ---------------------------------------------------------------------------
__global__ __launch_bounds__(256)
void prep(const float* __restrict__ x, const float* __restrict__ W2,
          const float* __restrict__ Wf, const float* __restrict__ b1,
          const float* __restrict__ b2) {
    __shared__ float ts[64][65];
    int bx = blockIdx.x, tid = threadIdx.x;
    if (bx < 256) {
        xscan_block(x, bx, bx * 128, tid);
    } else if (bx < 512) {
        int b2i = bx - 256;
        int i0 = (b2i & 31) * 64;
        int j0 = (b2i >> 5) * 64;
#pragma unroll
        for (int t = 0; t < 16; t++) {
            int e = tid + t * 256;
            int r = e >> 6, c = e & 63;
            ts[r][c] = W2[(size_t)(i0 + r) * H1 + j0 + c];
        }
        __syncthreads();
#pragma unroll
        for (int t = 0; t < 16; t++) {
            int e = tid + t * 256;
            int r = e >> 6, c = e & 63;
            g_w2t[(size_t)(j0 + r) * H2 + i0 + c] =
                __uint_as_float(f2tf(ts[c][r]));
        }
    } else if (bx < 544) {
        int base = (bx - 512) * 4096;
#pragma unroll
        for (int t = 0; t < 16; t++) {
            int i = base + tid + t * 256;
            float4 v = ((const float4*)Wf)[i];
            v.x = __uint_as_float(f2tf(v.x));
            v.y = __uint_as_float(f2tf(v.y));
            v.z = __uint_as_float(f2tf(v.z));
            v.w = __uint_as_float(f2tf(v.w));
            ((float4*)g_wfr)[i] = v;
        }
    } else if (bx < 800) {
        int w = tid >> 5, lane = tid & 31;
        int row = (bx - 544) * 8 + w;
        const float* wr = W2 + (size_t)row * H1;
        float s = 0.f;
#pragma unroll
        for (int i = 0; i < H1 / 32; i++)
            s += wr[lane + i * 32] * b1[lane + i * 32];
#pragma unroll
        for (int o = 16; o; o >>= 1) s += __shfl_xor_sync(~0u, s, o);
        if (lane == 0) g_t2[row] = s + b2[row];
    } else {
        int base = (bx - 800) * 4096;
        float4 z = make_float4(0.f, 0.f, 0.f, 0.f);
#pragma unroll
        for (int t = 0; t < 16; t++)
            ((float4*)g_t1)[base + tid + t * 256] = z;
    }
}

// ---------------------------------------------------------------------------
// K1 wchain (352 blocks, GEMM_SMEM dyn smem):
//   [0,64)   split-K(16) tf32 GEMM: T1 += Wf @ W2^T  (atomicAdd epilogue)
//   [64,96)  beff = Wf@t2 + bf
//   [96,352) bn x-scan second half (rows 32768..65535, 128 rows/block)
// ---------------------------------------------------------------------------
#define SMSTRIDE   36
#define ROWBYTES   (SMSTRIDE * 4)
#define A_BYTES    (128 * ROWBYTES)
#define B_BYTES    (256 * ROWBYTES)
#define STAGE_B    (A_BYTES + B_BYTES)
#define STAGES     3
#define GEMM_SMEM  (STAGES * STAGE_B)

__device__ __forceinline__ void issue_tile(const float* aPtr, const float* bPtr,
                                           uint32_t sA, uint32_t sB,
                                           int kOff, int K) {
#pragma unroll
    for (int j = 0; j < 4; j++)
        cp16(sA + j * 32 * ROWBYTES, aPtr + (size_t)j * 32 * K + kOff);
#pragma unroll
    for (int j = 0; j < 8; j++)
        cp16(sB + j * 32 * ROWBYTES, bPtr + (size_t)j * 32 * K + kOff);
}

__global__ __launch_bounds__(256, 1)
void wchain(const float* __restrict__ x, const float* __restrict__ Wf,
            const float* __restrict__ bf) {
    extern __shared__ char smem[];
    const int bx = blockIdx.x;
    const int tid = threadIdx.x;

    if (bx >= 96) {               // ---- bn x-scan, second half ----
        int part = (bx - 96) + 256;
        xscan_block(x, part, part * 128, tid);
        return;
    }
    if (bx >= 64) {               // ---- beff ----
        int w = tid >> 5, lane = tid & 31;
        int row = (bx - 64) * 8 + w;
        const float* wr = Wf + (size_t)row * H2;
        float s = 0.f;
#pragma unroll
        for (int i = 0; i < H2 / 32; i++)
            s += wr[lane + i * 32] * g_t2[lane + i * 32];
#pragma unroll
        for (int o = 16; o; o >>= 1) s += __shfl_xor_sync(~0u, s, o);
        if (lane == 0) g_beff[row] = s + bf[row];
        return;
    }

    // ---- split-K(16) GEMM: A=g_wfr [256,2048], W=g_w2t [512,2048], slice 128 ----
    const uint32_t sbase = smem_u32(smem);
    const int lane = tid & 31;
    const int g    = lane >> 2;
    const int tg   = lane & 3;
    const int wid  = tid >> 5;
    const int wm   = (wid & 1) * 64;
    const int wn   = (wid >> 1) * 64;

    const int xx = bx & 1, yy = (bx >> 1) & 1, z = bx >> 2;   // z: 0..15
    const int K = H2, kloop = 128, T = kloop >> 5;            // T = 4
    const float* A = g_wfr + z * kloop;
    const float* W = g_w2t + z * kloop;

    const size_t rowBase = (size_t)yy * 128;
    const size_t colBase = (size_t)xx * 256;

    const int r0 = tid >> 3;
    const int c0 = tid & 7;
    const float* aPtr = A + (rowBase + r0) * (size_t)K + c0 * 4;
    const float* bPtr = W + (colBase + r0) * (size_t)K + c0 * 4;
    const uint32_t sAo = r0 * ROWBYTES + c0 * 16;
    const uint32_t sBo = A_BYTES + r0 * ROWBYTES + c0 * 16;

    float acc[4][8][4];
#pragma unroll
    for (int mi = 0; mi < 4; mi++)
#pragma unroll
        for (int ni = 0; ni < 8; ni++)
#pragma unroll
            for (int k = 0; k < 4; k++) acc[mi][ni][k] = 0.f;

    issue_tile(aPtr, bPtr, sbase + sAo, sbase + sBo, 0, K);
    cp_commit();
    issue_tile(aPtr, bPtr, sbase + STAGE_B + sAo, sbase + STAGE_B + sBo, 32, K);
    cp_commit();

    for (int kt = 0; kt < T; kt++) {
        cp_wait<1>();
        __syncthreads();
        if (kt + 2 < T) {
            uint32_t sb2 = sbase + ((kt + 2) % STAGES) * STAGE_B;
            issue_tile(aPtr, bPtr, sb2 + sAo, sb2 + sBo, (kt + 2) * 32, K);
        }
        cp_commit();

        const unsigned* As = (const unsigned*)(smem + (kt % STAGES) * STAGE_B);
        const unsigned* Bs = (const unsigned*)(smem + (kt % STAGES) * STAGE_B + A_BYTES);
#pragma unroll
        for (int kk = 0; kk < 32; kk += 8) {
            unsigned a[4][4], b[8][2];
#pragma unroll
            for (int mi = 0; mi < 4; mi++) {
                int rr = wm + mi * 16;
                a[mi][0] = As[(rr + g)     * SMSTRIDE + kk + tg];
                a[mi][1] = As[(rr + g + 8) * SMSTRIDE + kk + tg];
                a[mi][2] = As[(rr + g)     * SMSTRIDE + kk + tg + 4];
                a[mi][3] = As[(rr + g + 8) * SMSTRIDE + kk + tg + 4];
            }
#pragma unroll
            for (int ni = 0; ni < 8; ni++) {
                int cc = wn + ni * 8 + g;
                b[ni][0] = Bs[cc * SMSTRIDE + kk + tg];
                b[ni][1] = Bs[cc * SMSTRIDE + kk + tg + 4];
            }
#pragma unroll
            for (int mi = 0; mi < 4; mi++)
#pragma unroll
                for (int ni = 0; ni < 8; ni++) {
                    asm volatile(
                        "mma.sync.aligned.m16n8k8.row.col.f32.tf32.tf32.f32 "
                        "{%0,%1,%2,%3}, {%4,%5,%6,%7}, {%8,%9}, {%0,%1,%2,%3};"
                        : "+f"(acc[mi][ni][0]), "+f"(acc[mi][ni][1]),
                          "+f"(acc[mi][ni][2]), "+f"(acc[mi][ni][3])
                        : "r"(a[mi][0]), "r"(a[mi][1]),
                          "r"(a[mi][2]), "r"(a[mi][3]),
                          "r"(b[ni][0]), "r"(b[ni][1]));
                }
        }
    }

#pragma unroll
    for (int mi = 0; mi < 4; mi++) {
        int row0 = (int)rowBase + wm + mi * 16 + g;
#pragma unroll
        for (int ni = 0; ni < 8; ni++) {
            int col = (int)colBase + wn + ni * 8 + 2 * tg;
            atomicAdd(&g_t1[row0 * H1 + col],           acc[mi][ni][0]);
            atomicAdd(&g_t1[row0 * H1 + col + 1],       acc[mi][ni][1]);
            atomicAdd(&g_t1[(row0 + 8) * H1 + col],     acc[mi][ni][2]);
            atomicAdd(&g_t1[(row0 + 8) * H1 + col + 1], acc[mi][ni][3]);
        }
    }
}

// ---------------------------------------------------------------------------
// K2 weff_k (72 blocks):
//   [0,64)  Weff = T1 @ W1 (fp32 FFMA 32x32 tiles, reg-prefetched) + round
//   [64,72) bn_final (512 partials)
// ---------------------------------------------------------------------------
__global__ __launch_bounds__(256)
void weff_k(const float* __restrict__ W1, const float* __restrict__ gamma,
            const float* __restrict__ beta) {
    int tid = threadIdx.x;
    if (blockIdx.x >= 64) {
        int c   = (blockIdx.x - 64) * 32 + (tid >> 3);
        int sub = tid & 7;
        float s = 0.f, q = 0.f;
#pragma unroll 8
        for (int b = sub; b < NPART; b += 8) {
            s += g_partS[b * 256 + c];
            q += g_partQ[b * 256 + c];
        }
#pragma unroll
        for (int o = 4; o; o >>= 1) {
            s += __shfl_xor_sync(~0u, s, o);
            q += __shfl_xor_sync(~0u, q, o);
        }
        if (sub == 0) {
            const float inv = 1.0f / (float)NROWS;
            float mu  = s * inv;
            float var = q * inv - mu * mu;
            float sc  = gamma[c] * rsqrtf(var + 1e-5f);
            g_scale[c] = sc;
            g_shift[c] = beta[c] - mu * sc;
        }
        return;
    }
    __shared__ float As[32][36], Bs[32][36];
    int i0 = (blockIdx.x >> 3) * 32, j0 = (blockIdx.x & 7) * 32;
    int ty = tid >> 4, tx = tid & 15;
    int lr = tid >> 3, lc4 = (tid & 7) * 4;
    float a00 = 0.f, a01 = 0.f, a10 = 0.f, a11 = 0.f;

    float4 ra = *(const float4*)(&g_t1[(i0 + lr) * H1 + lc4]);
    float4 rb = *(const float4*)(&W1[(size_t)lr * DIM + j0 + lc4]);

    for (int kb = 0; kb < H1; kb += 32) {
        *(float4*)(&As[lr][lc4]) = ra;
        *(float4*)(&Bs[lr][lc4]) = rb;
        __syncthreads();
        if (kb + 32 < H1) {
            ra = *(const float4*)(&g_t1[(i0 + lr) * H1 + kb + 32 + lc4]);
            rb = *(const float4*)(&W1[(size_t)(kb + 32 + lr) * DIM + j0 + lc4]);
        }
#pragma unroll
        for (int k = 0; k < 32; k++) {
            float x0 = As[ty * 2][k],     x1 = As[ty * 2 + 1][k];
            float y0 = Bs[k][tx * 2],     y1 = Bs[k][tx * 2 + 1];
            a00 = fmaf(x0, y0, a00); a01 = fmaf(x0, y1, a01);
            a10 = fmaf(x1, y0, a10); a11 = fmaf(x1, y1, a11);
        }
        __syncthreads();
    }
    int r0 = i0 + ty * 2, c0 = j0 + tx * 2;
    g_weff[r0 * DIM + c0]           = __uint_as_float(f2tf(a00));
    g_weff[r0 * DIM + c0 + 1]       = __uint_as_float(f2tf(a01));
    g_weff[(r0 + 1) * DIM + c0]     = __uint_as_float(f2tf(a10));
    g_weff[(r0 + 1) * DIM + c0 + 1] = __uint_as_float(f2tf(a11));
}

// ---------------------------------------------------------------------------
// K3 fused final: 128x128 CTA tile, 128 threads (4 warps of 64x64), 2 CTAs/SM.
// A double-buffered (generated in-kernel), B double-buffered (cp.async).
// grid (2, 512): blockIdx.x = column half; col-half 0 also writes raw.
// smem: A[2][18432] | B[2][18432] = 73728 B.   (exact R10 kernel)
// ---------------------------------------------------------------------------
#define FA_STAGE 18432
#define FB_OFF   (2 * FA_STAGE)
#define F_SMEM   (4 * FA_STAGE)        // 73728

__device__ __forceinline__ void issueB_f(uint32_t sbase, int slot, int kt,
                                         int tid, int colBase) {
#pragma unroll
    for (int j = 0; j < 8; j++) {
        int r = (tid >> 3) + j * 16;
        cp16(sbase + FB_OFF + slot * FA_STAGE + r * ROWBYTES + (tid & 7) * 16,
             g_weff + (colBase + r) * 256 + kt * 32 + (tid & 7) * 4);
    }
}

__global__ __launch_bounds__(128, 2)
void fused_final(const float* __restrict__ x, float* __restrict__ raw,
                 float* __restrict__ out) {
    extern __shared__ char smem[];
    const uint32_t sbase = smem_u32(smem);
    const int tid  = threadIdx.x;
    const int lane = tid & 31;
    const int g    = lane >> 2;
    const int tg   = lane & 3;
    const int wid  = tid >> 5;            // 0..3
    const int wm   = (wid & 1) * 64;
    const int wn   = (wid >> 1) * 64;
    const int colBase = blockIdx.x * 128;
    const bool doRaw  = (blockIdx.x == 0);
    const size_t rowBase = (size_t)blockIdx.y * 128;

    issueB_f(sbase, 0, 0, tid, colBase);
    cp_commit();
    issueB_f(sbase, 1, 1, tid, colBase);
    cp_commit();

    // A-gen geometry: thread covers 8 rows (r = tid>>3 + 16j), fixed f4 col cf
    const int cf = tid & 7;
    const int ar0 = tid >> 3;             // 0..15
    const float* xp0 = x   + (rowBase + ar0) * 256 + cf * 4;
    float*       rp0 = raw + (rowBase + ar0) * 256 + cf * 4;
    const uint32_t so0 = ar0 * ROWBYTES + cf * 16;

    // generate chunk 0 into A slot 0
    float4 nv[8];
#pragma unroll
    for (int j = 0; j < 8; j++) nv[j] = *(const float4*)(xp0 + j * 4096);
    {
        float4 sc = ((const float4*)g_scale)[cf];
        float4 sh = ((const float4*)g_shift)[cf];
#pragma unroll
        for (int j = 0; j < 8; j++) {
            float4 xn;
            xn.x = fmaf(nv[j].x, sc.x, sh.x);
            xn.y = fmaf(nv[j].y, sc.y, sh.y);
            xn.z = fmaf(nv[j].z, sc.z, sh.z);
            xn.w = fmaf(nv[j].w, sc.w, sh.w);
            if (doRaw) {
                float4 t;
                t.x = tanh_ap(xn.x); t.y = tanh_ap(xn.y);
                t.z = tanh_ap(xn.z); t.w = tanh_ap(xn.w);
                *(float4*)(rp0 + j * 4096) = t;
            }
            uint4 rb;
            rb.x = f2tf(xn.x); rb.y = f2tf(xn.y);
            rb.z = f2tf(xn.z); rb.w = f2tf(xn.w);
            *(uint4*)(smem + so0 + j * 16 * ROWBYTES) = rb;
        }
    }

    float acc[4][8][4];
#pragma unroll
    for (int mi = 0; mi < 4; mi++)
#pragma unroll
        for (int ni = 0; ni < 8; ni++)
#pragma unroll
            for (int k = 0; k < 4; k++) acc[mi][ni][k] = 0.f;

    for (int kt = 0; kt < 8; kt++) {
        if (kt < 7) {
#pragma unroll
            for (int j = 0; j < 8; j++)
                nv[j] = *(const float4*)(xp0 + j * 4096 + (kt + 1) * 32);
        }
        cp_wait<1>();
        __syncthreads();

        const unsigned* As = (const unsigned*)(smem + (kt & 1) * FA_STAGE);
        const unsigned* Bs = (const unsigned*)(smem + FB_OFF + (kt & 1) * FA_STAGE);
#pragma unroll
        for (int kk = 0; kk < 32; kk += 8) {
            unsigned a[4][4], b[8][2];
#pragma unroll
            for (int mi = 0; mi < 4; mi++) {
                int rr = wm + mi * 16;
                a[mi][0] = As[(rr + g)     * SMSTRIDE + kk + tg];
                a[mi][1] = As[(rr + g + 8) * SMSTRIDE + kk + tg];
                a[mi][2] = As[(rr + g)     * SMSTRIDE + kk + tg + 4];
                a[mi][3] = As[(rr + g + 8) * SMSTRIDE + kk + tg + 4];
            }
#pragma unroll
            for (int ni = 0; ni < 8; ni++) {
                int cc = wn + ni * 8 + g;
                b[ni][0] = Bs[cc * SMSTRIDE + kk + tg];
                b[ni][1] = Bs[cc * SMSTRIDE + kk + tg + 4];
            }
#pragma unroll
            for (int mi = 0; mi < 4; mi++)
#pragma unroll
                for (int ni = 0; ni < 8; ni++) {
                    asm volatile(
                        "mma.sync.aligned.m16n8k8.row.col.f32.tf32.tf32.f32 "
                        "{%0,%1,%2,%3}, {%4,%5,%6,%7}, {%8,%9}, {%0,%1,%2,%3};"
                        : "+f"(acc[mi][ni][0]), "+f"(acc[mi][ni][1]),
                          "+f"(acc[mi][ni][2]), "+f"(acc[mi][ni][3])
                        : "r"(a[mi][0]), "r"(a[mi][1]),
                          "r"(a[mi][2]), "r"(a[mi][3]),
                          "r"(b[ni][0]), "r"(b[ni][1]));
                }
        }

        // generate chunk kt+1 into A slot (kt+1)&1
        if (kt < 7) {
            float4 sc = ((const float4*)g_scale)[(kt + 1) * 8 + cf];
            float4 sh = ((const float4*)g_shift)[(kt + 1) * 8 + cf];
#pragma unroll
            for (int j = 0; j < 8; j++) {
                float4 xn;
                xn.x = fmaf(nv[j].x, sc.x, sh.x);
                xn.y = fmaf(nv[j].y, sc.y, sh.y);
                xn.z = fmaf(nv[j].z, sc.z, sh.z);
                xn.w = fmaf(nv[j].w, sc.w, sh.w);
                if (doRaw) {
                    float4 t;
                    t.x = tanh_ap(xn.x); t.y = tanh_ap(xn.y);
                    t.z = tanh_ap(xn.z); t.w = tanh_ap(xn.w);
                    *(float4*)(rp0 + j * 4096 + (kt + 1) * 32) = t;
                }
                uint4 rb;
                rb.x = f2tf(xn.x); rb.y = f2tf(xn.y);
                rb.z = f2tf(xn.z); rb.w = f2tf(xn.w);
                *(uint4*)(smem + ((kt + 1) & 1) * FA_STAGE + so0 +
                          j * 16 * ROWBYTES) = rb;
            }
        }
        __syncthreads();               // all warps done reading B slot kt&1
        if (kt + 2 < 8) issueB_f(sbase, kt & 1, kt + 2, tid, colBase);
        cp_commit();
    }

    // epilogue: + beff, tanh, store
#pragma unroll
    for (int mi = 0; mi < 4; mi++) {
        size_t row0 = rowBase + wm + mi * 16 + g;
#pragma unroll
        for (int ni = 0; ni < 8; ni++) {
            int col = colBase + wn + ni * 8 + 2 * tg;
            float v0 = tanh_ap(acc[mi][ni][0] + g_beff[col]);
            float v1 = tanh_ap(acc[mi][ni][1] + g_beff[col + 1]);
            float v2 = tanh_ap(acc[mi][ni][2] + g_beff[col]);
            float v3 = tanh_ap(acc[mi][ni][3] + g_beff[col + 1]);
            *(float2*)&out[row0 * 256 + col]       = make_float2(v0, v1);
            *(float2*)&out[(row0 + 8) * 256 + col] = make_float2(v2, v3);
        }
    }
}

// ---------------------------------------------------------------------------
// Launch (4 kernels)
// ---------------------------------------------------------------------------
extern "C" void kernel_launch(void* const* d_in, const int* in_sizes, int n_in,
                              void* d_out, int out_size) {
    const float* x     = (const float*)d_in[0];
    const float* gamma = (const float*)d_in[1];
    const float* beta  = (const float*)d_in[2];
    const float* W1    = (const float*)d_in[3];
    const float* b1    = (const float*)d_in[4];
    const float* W2    = (const float*)d_in[5];
    const float* b2    = (const float*)d_in[6];
    const float* Wf    = (const float*)d_in[7];
    const float* bf    = (const float*)d_in[8];

    float* out = (float*)d_out;
    float* raw = out + (size_t)NROWS * DIM;

    cudaFuncSetAttribute(wchain,
                         cudaFuncAttributeMaxDynamicSharedMemorySize, GEMM_SMEM);
    cudaFuncSetAttribute(fused_final,
                         cudaFuncAttributeMaxDynamicSharedMemorySize, F_SMEM);

    prep<<<808, 256>>>(x, W2, Wf, b1, b2);
    wchain<<<352, 256, GEMM_SMEM>>>(x, Wf, bf);
    weff_k<<<72, 256>>>(W1, gamma, beta);
    fused_final<<<dim3(2, NROWS / 128), 128, F_SMEM>>>(x, raw, out);
}

// round 14
// speedup vs baseline: 1.1837x; 1.0427x over previous
#include <cuda_runtime.h>
#include <math.h>
#include <cstdint>

#define NROWS 65536
#define DIM   256
#define H1    512
#define H2    2048
#define NPART 512

// ---------------------------------------------------------------------------
// Device scratch (allocation-free rule)
// ---------------------------------------------------------------------------
__device__ __align__(16) float g_partS[NPART * 256];
__device__ __align__(16) float g_partQ[NPART * 256];
__device__ __align__(16) float g_scale[DIM];
__device__ __align__(16) float g_shift[DIM];
__device__ __align__(16) float g_w2t[H1 * H2];        // W2^T rounded [512,2048]
__device__ __align__(16) float g_wfr[DIM * H2];       // Wf rounded   [256,2048]
__device__ __align__(16) float g_t2[H2];              // W2@b1 + b2
__device__ __align__(16) float g_beff[DIM];           // Wf@t2 + bf
__device__ __align__(16) float g_t1[DIM * H1];        // T1 = Wf@W2 fp32 (atomic acc)
__device__ __align__(16) float g_weff[DIM * DIM];     // Wf@W2@W1 rounded [256,256]

// ---------------------------------------------------------------------------
// Helpers
// ---------------------------------------------------------------------------
__device__ __forceinline__ unsigned f2tf(float f) {
    unsigned u;
    asm("cvt.rna.tf32.f32 %0, %1;" : "=r"(u) : "f"(f));
    return u;
}
__device__ __forceinline__ float tanh_ap(float x) {
    float r;
    asm("tanh.approx.f32 %0, %1;" : "=f"(r) : "f"(x));
    return r;
}
__device__ __forceinline__ uint32_t smem_u32(const void* p) {
    uint32_t a;
    asm("{ .reg .u64 t; cvta.to.shared.u64 t, %1; cvt.u32.u64 %0, t; }"
        : "=r"(a) : "l"(p));
    return a;
}
__device__ __forceinline__ void cp16(uint32_t dst, const void* src) {
    asm volatile("cp.async.cg.shared.global [%0], [%1], 16;"
                 :: "r"(dst), "l"(src));
}
__device__ __forceinline__ void cp_commit() {
    asm volatile("cp.async.commit_group;" ::: "memory");
}
template <int N>
__device__ __forceinline__ void cp_wait() {
    asm volatile("cp.async.wait_group %0;" :: "n"(N) : "memory");
}

// x-scan helper: one block reduces 128 rows starting at row0 into partial id
__device__ __forceinline__ void xscan_block(const float* __restrict__ x,
                                            int part_id, int row0, int tid) {
    __shared__ float4 rs[4][64], rq[4][64];
    int rg = tid >> 6;                 // 0..3 row groups (32 rows each)
    int tc = tid & 63;                 // float4 column
    const float4* xp = (const float4*)(x + (size_t)(row0 + rg * 32) * DIM) + tc;
    float4 s = make_float4(0.f, 0.f, 0.f, 0.f);
    float4 q = make_float4(0.f, 0.f, 0.f, 0.f);
#pragma unroll 16
    for (int i = 0; i < 32; i++) {
        float4 v = xp[(size_t)i * 64];
        s.x += v.x; s.y += v.y; s.z += v.z; s.w += v.w;
        q.x += v.x * v.x; q.y += v.y * v.y;
        q.z += v.z * v.z; q.w += v.w * v.w;
    }
    rs[rg][tc] = s; rq[rg][tc] = q;
    __syncthreads();
    if (rg == 0) {
#pragma unroll
        for (int z = 1; z < 4; z++) {
            float4 a = rs[z][tc], b = rq[z][tc];
            s.x += a.x; s.y += a.y; s.z += a.z; s.w += a.w;
            q.x += b.x; q.y += b.y; q.z += b.z; q.w += b.w;
        }
        ((float4*)(g_partS + part_id * 256))[tc] = s;
        ((float4*)(g_partQ + part_id * 256))[tc] = q;
    }
}

// ---------------------------------------------------------------------------
// K0 prep (808 blocks):
//   [0,256)   bn x-scan first half (rows 0..32767, 128 rows/block)
//   [256,512) W2 transpose + tf32 round -> g_w2t
//   [512,544) round Wf -> g_wfr
//   [544,800) t2 = W2@b1 + b2
//   [800,808) zero g_t1
// ---------------------------------------------------------------------------
__global__ __launch_bounds__(256)
void prep(const float* __restrict__ x, const float* __restrict__ W2,
          const float* __restrict__ Wf, const float* __restrict__ b1,
          const float* __restrict__ b2) {
    __shared__ float ts[64][65];
    int bx = blockIdx.x, tid = threadIdx.x;
    if (bx < 256) {
        xscan_block(x, bx, bx * 128, tid);
    } else if (bx < 512) {
        int b2i = bx - 256;
        int i0 = (b2i & 31) * 64;
        int j0 = (b2i >> 5) * 64;
#pragma unroll
        for (int t = 0; t < 16; t++) {
            int e = tid + t * 256;
            int r = e >> 6, c = e & 63;
            ts[r][c] = W2[(size_t)(i0 + r) * H1 + j0 + c];
        }
        __syncthreads();
#pragma unroll
        for (int t = 0; t < 16; t++) {
            int e = tid + t * 256;
            int r = e >> 6, c = e & 63;
            g_w2t[(size_t)(j0 + r) * H2 + i0 + c] =
                __uint_as_float(f2tf(ts[c][r]));
        }
    } else if (bx < 544) {
        int base = (bx - 512) * 4096;
#pragma unroll
        for (int t = 0; t < 16; t++) {
            int i = base + tid + t * 256;
            float4 v = ((const float4*)Wf)[i];
            v.x = __uint_as_float(f2tf(v.x));
            v.y = __uint_as_float(f2tf(v.y));
            v.z = __uint_as_float(f2tf(v.z));
            v.w = __uint_as_float(f2tf(v.w));
            ((float4*)g_wfr)[i] = v;
        }
    } else if (bx < 800) {
        int w = tid >> 5, lane = tid & 31;
        int row = (bx - 544) * 8 + w;
        const float* wr = W2 + (size_t)row * H1;
        float s = 0.f;
#pragma unroll
        for (int i = 0; i < H1 / 32; i++)
            s += wr[lane + i * 32] * b1[lane + i * 32];
#pragma unroll
        for (int o = 16; o; o >>= 1) s += __shfl_xor_sync(~0u, s, o);
        if (lane == 0) g_t2[row] = s + b2[row];
    } else {
        int base = (bx - 800) * 4096;
        float4 z = make_float4(0.f, 0.f, 0.f, 0.f);
#pragma unroll
        for (int t = 0; t < 16; t++)
            ((float4*)g_t1)[base + tid + t * 256] = z;
    }
}

// ---------------------------------------------------------------------------
// K1 wchain (352 blocks, GEMM_SMEM dyn smem):
//   [0,64)   split-K(16) tf32 GEMM: T1 += Wf @ W2^T  (atomicAdd epilogue)
//   [64,96)  beff = Wf@t2 + bf
//   [96,352) bn x-scan second half (rows 32768..65535, 128 rows/block)
// ---------------------------------------------------------------------------
#define SMSTRIDE   36
#define ROWBYTES   (SMSTRIDE * 4)
#define A_BYTES    (128 * ROWBYTES)
#define B_BYTES    (256 * ROWBYTES)
#define STAGE_B    (A_BYTES + B_BYTES)
#define STAGES     3
#define GEMM_SMEM  (STAGES * STAGE_B)

__device__ __forceinline__ void issue_tile(const float* aPtr, const float* bPtr,
                                           uint32_t sA, uint32_t sB,
                                           int kOff, int K) {
#pragma unroll
    for (int j = 0; j < 4; j++)
        cp16(sA + j * 32 * ROWBYTES, aPtr + (size_t)j * 32 * K + kOff);
#pragma unroll
    for (int j = 0; j < 8; j++)
        cp16(sB + j * 32 * ROWBYTES, bPtr + (size_t)j * 32 * K + kOff);
}

__global__ __launch_bounds__(256, 1)
void wchain(const float* __restrict__ x, const float* __restrict__ Wf,
            const float* __restrict__ bf) {
    extern __shared__ char smem[];
    const int bx = blockIdx.x;
    const int tid = threadIdx.x;

    if (bx >= 96) {               // ---- bn x-scan, second half ----
        int part = (bx - 96) + 256;
        xscan_block(x, part, part * 128, tid);
        return;
    }
    if (bx >= 64) {               // ---- beff ----
        int w = tid >> 5, lane = tid & 31;
        int row = (bx - 64) * 8 + w;
        const float* wr = Wf + (size_t)row * H2;
        float s = 0.f;
#pragma unroll
        for (int i = 0; i < H2 / 32; i++)
            s += wr[lane + i * 32] * g_t2[lane + i * 32];
#pragma unroll
        for (int o = 16; o; o >>= 1) s += __shfl_xor_sync(~0u, s, o);
        if (lane == 0) g_beff[row] = s + bf[row];
        return;
    }

    // ---- split-K(16) GEMM: A=g_wfr [256,2048], W=g_w2t [512,2048], slice 128 ----
    const uint32_t sbase = smem_u32(smem);
    const int lane = tid & 31;
    const int g    = lane >> 2;
    const int tg   = lane & 3;
    const int wid  = tid >> 5;
    const int wm   = (wid & 1) * 64;
    const int wn   = (wid >> 1) * 64;

    const int xx = bx & 1, yy = (bx >> 1) & 1, z = bx >> 2;   // z: 0..15
    const int K = H2, kloop = 128, T = kloop >> 5;            // T = 4
    const float* A = g_wfr + z * kloop;
    const float* W = g_w2t + z * kloop;

    const size_t rowBase = (size_t)yy * 128;
    const size_t colBase = (size_t)xx * 256;

    const int r0 = tid >> 3;
    const int c0 = tid & 7;
    const float* aPtr = A + (rowBase + r0) * (size_t)K + c0 * 4;
    const float* bPtr = W + (colBase + r0) * (size_t)K + c0 * 4;
    const uint32_t sAo = r0 * ROWBYTES + c0 * 16;
    const uint32_t sBo = A_BYTES + r0 * ROWBYTES + c0 * 16;

    float acc[4][8][4];
#pragma unroll
    for (int mi = 0; mi < 4; mi++)
#pragma unroll
        for (int ni = 0; ni < 8; ni++)
#pragma unroll
            for (int k = 0; k < 4; k++) acc[mi][ni][k] = 0.f;

    issue_tile(aPtr, bPtr, sbase + sAo, sbase + sBo, 0, K);
    cp_commit();
    issue_tile(aPtr, bPtr, sbase + STAGE_B + sAo, sbase + STAGE_B + sBo, 32, K);
    cp_commit();

    for (int kt = 0; kt < T; kt++) {
        cp_wait<1>();
        __syncthreads();
        if (kt + 2 < T) {
            uint32_t sb2 = sbase + ((kt + 2) % STAGES) * STAGE_B;
            issue_tile(aPtr, bPtr, sb2 + sAo, sb2 + sBo, (kt + 2) * 32, K);
        }
        cp_commit();

        const unsigned* As = (const unsigned*)(smem + (kt % STAGES) * STAGE_B);
        const unsigned* Bs = (const unsigned*)(smem + (kt % STAGES) * STAGE_B + A_BYTES);
#pragma unroll
        for (int kk = 0; kk < 32; kk += 8) {
            unsigned a[4][4], b[8][2];
#pragma unroll
            for (int mi = 0; mi < 4; mi++) {
                int rr = wm + mi * 16;
                a[mi][0] = As[(rr + g)     * SMSTRIDE + kk + tg];
                a[mi][1] = As[(rr + g + 8) * SMSTRIDE + kk + tg];
                a[mi][2] = As[(rr + g)     * SMSTRIDE + kk + tg + 4];
                a[mi][3] = As[(rr + g + 8) * SMSTRIDE + kk + tg + 4];
            }
#pragma unroll
            for (int ni = 0; ni < 8; ni++) {
                int cc = wn + ni * 8 + g;
                b[ni][0] = Bs[cc * SMSTRIDE + kk + tg];
                b[ni][1] = Bs[cc * SMSTRIDE + kk + tg + 4];
            }
#pragma unroll
            for (int mi = 0; mi < 4; mi++)
#pragma unroll
                for (int ni = 0; ni < 8; ni++) {
                    asm volatile(
                        "mma.sync.aligned.m16n8k8.row.col.f32.tf32.tf32.f32 "
                        "{%0,%1,%2,%3}, {%4,%5,%6,%7}, {%8,%9}, {%0,%1,%2,%3};"
                        : "+f"(acc[mi][ni][0]), "+f"(acc[mi][ni][1]),
                          "+f"(acc[mi][ni][2]), "+f"(acc[mi][ni][3])
                        : "r"(a[mi][0]), "r"(a[mi][1]),
                          "r"(a[mi][2]), "r"(a[mi][3]),
                          "r"(b[ni][0]), "r"(b[ni][1]));
                }
        }
    }

#pragma unroll
    for (int mi = 0; mi < 4; mi++) {
        int row0 = (int)rowBase + wm + mi * 16 + g;
#pragma unroll
        for (int ni = 0; ni < 8; ni++) {
            int col = (int)colBase + wn + ni * 8 + 2 * tg;
            atomicAdd(&g_t1[row0 * H1 + col],           acc[mi][ni][0]);
            atomicAdd(&g_t1[row0 * H1 + col + 1],       acc[mi][ni][1]);
            atomicAdd(&g_t1[(row0 + 8) * H1 + col],     acc[mi][ni][2]);
            atomicAdd(&g_t1[(row0 + 8) * H1 + col + 1], acc[mi][ni][3]);
        }
    }
}

// ---------------------------------------------------------------------------
// K2 weff_k (72 blocks):
//   [0,64)  Weff = T1 @ W1 (fp32 FFMA 32x32 tiles, reg-prefetched) + round
//   [64,72) bn_final (512 partials)
// ---------------------------------------------------------------------------
__global__ __launch_bounds__(256)
void weff_k(const float* __restrict__ W1, const float* __restrict__ gamma,
            const float* __restrict__ beta) {
    int tid = threadIdx.x;
    if (blockIdx.x >= 64) {
        int c   = (blockIdx.x - 64) * 32 + (tid >> 3);
        int sub = tid & 7;
        float s = 0.f, q = 0.f;
#pragma unroll 8
        for (int b = sub; b < NPART; b += 8) {
            s += g_partS[b * 256 + c];
            q += g_partQ[b * 256 + c];
        }
#pragma unroll
        for (int o = 4; o; o >>= 1) {
            s += __shfl_xor_sync(~0u, s, o);
            q += __shfl_xor_sync(~0u, q, o);
        }
        if (sub == 0) {
            const float inv = 1.0f / (float)NROWS;
            float mu  = s * inv;
            float var = q * inv - mu * mu;
            float sc  = gamma[c] * rsqrtf(var + 1e-5f);
            g_scale[c] = sc;
            g_shift[c] = beta[c] - mu * sc;
        }
        return;
    }
    __shared__ float As[32][36], Bs[32][36];
    int i0 = (blockIdx.x >> 3) * 32, j0 = (blockIdx.x & 7) * 32;
    int ty = tid >> 4, tx = tid & 15;
    int lr = tid >> 3, lc4 = (tid & 7) * 4;
    float a00 = 0.f, a01 = 0.f, a10 = 0.f, a11 = 0.f;

    float4 ra = *(const float4*)(&g_t1[(i0 + lr) * H1 + lc4]);
    float4 rb = *(const float4*)(&W1[(size_t)lr * DIM + j0 + lc4]);

    for (int kb = 0; kb < H1; kb += 32) {
        *(float4*)(&As[lr][lc4]) = ra;
        *(float4*)(&Bs[lr][lc4]) = rb;
        __syncthreads();
        if (kb + 32 < H1) {
            ra = *(const float4*)(&g_t1[(i0 + lr) * H1 + kb + 32 + lc4]);
            rb = *(const float4*)(&W1[(size_t)(kb + 32 + lr) * DIM + j0 + lc4]);
        }
#pragma unroll
        for (int k = 0; k < 32; k++) {
            float x0 = As[ty * 2][k],     x1 = As[ty * 2 + 1][k];
            float y0 = Bs[k][tx * 2],     y1 = Bs[k][tx * 2 + 1];
            a00 = fmaf(x0, y0, a00); a01 = fmaf(x0, y1, a01);
            a10 = fmaf(x1, y0, a10); a11 = fmaf(x1, y1, a11);
        }
        __syncthreads();
    }
    int r0 = i0 + ty * 2, c0 = j0 + tx * 2;
    g_weff[r0 * DIM + c0]           = __uint_as_float(f2tf(a00));
    g_weff[r0 * DIM + c0 + 1]       = __uint_as_float(f2tf(a01));
    g_weff[(r0 + 1) * DIM + c0]     = __uint_as_float(f2tf(a10));
    g_weff[(r0 + 1) * DIM + c0 + 1] = __uint_as_float(f2tf(a11));
}

// ---------------------------------------------------------------------------
// K3 fused final: 128x128 CTA tile, 128 threads (4 warps of 64x64), 2 CTAs/SM.
// A double-buffered (generated in-kernel), B TRIPLE-buffered (cp.async) --
// one __syncthreads per chunk: issueB after sync targets the slot last read
// in MMA(kt-1), which all warps finished before sync1(kt).
// smem: A[2][18432] | B[3][18432] = 92160 B.
// ---------------------------------------------------------------------------
#define FA_STAGE 18432
#define FB_OFF   (2 * FA_STAGE)
#define F_SMEM   (5 * FA_STAGE)        // 92160

__device__ __forceinline__ void issueB_f(uint32_t sbase, int slot, int kt,
                                         int tid, int colBase) {
#pragma unroll
    for (int j = 0; j < 8; j++) {
        int r = (tid >> 3) + j * 16;
        cp16(sbase + FB_OFF + slot * FA_STAGE + r * ROWBYTES + (tid & 7) * 16,
             g_weff + (colBase + r) * 256 + kt * 32 + (tid & 7) * 4);
    }
}

__global__ __launch_bounds__(128, 2)
void fused_final(const float* __restrict__ x, float* __restrict__ raw,
                 float* __restrict__ out) {
    extern __shared__ char smem[];
    const uint32_t sbase = smem_u32(smem);
    const int tid  = threadIdx.x;
    const int lane = tid & 31;
    const int g    = lane >> 2;
    const int tg   = lane & 3;
    const int wid  = tid >> 5;            // 0..3
    const int wm   = (wid & 1) * 64;
    const int wn   = (wid >> 1) * 64;
    const int colBase = blockIdx.x * 128;
    const bool doRaw  = (blockIdx.x == 0);
    const size_t rowBase = (size_t)blockIdx.y * 128;

    issueB_f(sbase, 0, 0, tid, colBase);
    cp_commit();
    issueB_f(sbase, 1, 1, tid, colBase);
    cp_commit();

    // A-gen geometry: thread covers 8 rows (r = tid>>3 + 16j), fixed f4 col cf
    const int cf = tid & 7;
    const int ar0 = tid >> 3;             // 0..15
    const float* xp0 = x   + (rowBase + ar0) * 256 + cf * 4;
    float*       rp0 = raw + (rowBase + ar0) * 256 + cf * 4;
    const uint32_t so0 = ar0 * ROWBYTES + cf * 16;

    // generate chunk 0 into A slot 0
    float4 nv[8];
#pragma unroll
    for (int j = 0; j < 8; j++) nv[j] = *(const float4*)(xp0 + j * 4096);
    {
        float4 sc = ((const float4*)g_scale)[cf];
        float4 sh = ((const float4*)g_shift)[cf];
#pragma unroll
        for (int j = 0; j < 8; j++) {
            float4 xn;
            xn.x = fmaf(nv[j].x, sc.x, sh.x);
            xn.y = fmaf(nv[j].y, sc.y, sh.y);
            xn.z = fmaf(nv[j].z, sc.z, sh.z);
            xn.w = fmaf(nv[j].w, sc.w, sh.w);
            if (doRaw) {
                float4 t;
                t.x = tanh_ap(xn.x); t.y = tanh_ap(xn.y);
                t.z = tanh_ap(xn.z); t.w = tanh_ap(xn.w);
                *(float4*)(rp0 + j * 4096) = t;
            }
            uint4 rb;
            rb.x = f2tf(xn.x); rb.y = f2tf(xn.y);
            rb.z = f2tf(xn.z); rb.w = f2tf(xn.w);
            *(uint4*)(smem + so0 + j * 16 * ROWBYTES) = rb;
        }
    }

    float acc[4][8][4];
#pragma unroll
    for (int mi = 0; mi < 4; mi++)
#pragma unroll
        for (int ni = 0; ni < 8; ni++)
#pragma unroll
            for (int k = 0; k < 4; k++) acc[mi][ni][k] = 0.f;

    for (int kt = 0; kt < 8; kt++) {
        if (kt < 7) {
#pragma unroll
            for (int j = 0; j < 8; j++)
                nv[j] = *(const float4*)(xp0 + j * 4096 + (kt + 1) * 32);
        }
        cp_wait<1>();
        __syncthreads();               // single barrier per chunk

        const unsigned* As = (const unsigned*)(smem + (kt & 1) * FA_STAGE);
        const unsigned* Bs = (const unsigned*)(smem + FB_OFF + (kt % 3) * FA_STAGE);
#pragma unroll
        for (int kk = 0; kk < 32; kk += 8) {
            unsigned a[4][4], b[8][2];
#pragma unroll
            for (int mi = 0; mi < 4; mi++) {
                int rr = wm + mi * 16;
                a[mi][0] = As[(rr + g)     * SMSTRIDE + kk + tg];
                a[mi][1] = As[(rr + g + 8) * SMSTRIDE + kk + tg];
                a[mi][2] = As[(rr + g)     * SMSTRIDE + kk + tg + 4];
                a[mi][3] = As[(rr + g + 8) * SMSTRIDE + kk + tg + 4];
            }
#pragma unroll
            for (int ni = 0; ni < 8; ni++) {
                int cc = wn + ni * 8 + g;
                b[ni][0] = Bs[cc * SMSTRIDE + kk + tg];
                b[ni][1] = Bs[cc * SMSTRIDE + kk + tg + 4];
            }
#pragma unroll
            for (int mi = 0; mi < 4; mi++)
#pragma unroll
                for (int ni = 0; ni < 8; ni++) {
                    asm volatile(
                        "mma.sync.aligned.m16n8k8.row.col.f32.tf32.tf32.f32 "
                        "{%0,%1,%2,%3}, {%4,%5,%6,%7}, {%8,%9}, {%0,%1,%2,%3};"
                        : "+f"(acc[mi][ni][0]), "+f"(acc[mi][ni][1]),
                          "+f"(acc[mi][ni][2]), "+f"(acc[mi][ni][3])
                        : "r"(a[mi][0]), "r"(a[mi][1]),
                          "r"(a[mi][2]), "r"(a[mi][3]),
                          "r"(b[ni][0]), "r"(b[ni][1]));
                }
        }

        // generate chunk kt+1 into A slot (kt+1)&1 (slot last read in MMA(kt-1),
        // which all warps finished before this chunk's barrier)
        if (kt < 7) {
            float4 sc = ((const float4*)g_scale)[(kt + 1) * 8 + cf];
            float4 sh = ((const float4*)g_shift)[(kt + 1) * 8 + cf];
#pragma unroll
            for (int j = 0; j < 8; j++) {
                float4 xn;
                xn.x = fmaf(nv[j].x, sc.x, sh.x);
                xn.y = fmaf(nv[j].y, sc.y, sh.y);
                xn.z = fmaf(nv[j].z, sc.z, sh.z);
                xn.w = fmaf(nv[j].w, sc.w, sh.w);
                if (doRaw) {
                    float4 t;
                    t.x = tanh_ap(xn.x); t.y = tanh_ap(xn.y);
                    t.z = tanh_ap(xn.z); t.w = tanh_ap(xn.w);
                    *(float4*)(rp0 + j * 4096 + (kt + 1) * 32) = t;
                }
                uint4 rb;
                rb.x = f2tf(xn.x); rb.y = f2tf(xn.y);
                rb.z = f2tf(xn.z); rb.w = f2tf(xn.w);
                *(uint4*)(smem + ((kt + 1) & 1) * FA_STAGE + so0 +
                          j * 16 * ROWBYTES) = rb;
            }
        }
        // B slot (kt+2)%3 == (kt-1)%3: last read in MMA(kt-1); safe after sync1(kt)
        if (kt + 2 < 8) issueB_f(sbase, (kt + 2) % 3, kt + 2, tid, colBase);
        cp_commit();
    }

    // epilogue: + beff, tanh, store
#pragma unroll
    for (int mi = 0; mi < 4; mi++) {
        size_t row0 = rowBase + wm + mi * 16 + g;
#pragma unroll
        for (int ni = 0; ni < 8; ni++) {
            int col = colBase + wn + ni * 8 + 2 * tg;
            float v0 = tanh_ap(acc[mi][ni][0] + g_beff[col]);
            float v1 = tanh_ap(acc[mi][ni][1] + g_beff[col + 1]);
            float v2 = tanh_ap(acc[mi][ni][2] + g_beff[col]);
            float v3 = tanh_ap(acc[mi][ni][3] + g_beff[col + 1]);
            *(float2*)&out[row0 * 256 + col]       = make_float2(v0, v1);
            *(float2*)&out[(row0 + 8) * 256 + col] = make_float2(v2, v3);
        }
    }
}

// ---------------------------------------------------------------------------
// Launch (4 kernels)
// ---------------------------------------------------------------------------
extern "C" void kernel_launch(void* const* d_in, const int* in_sizes, int n_in,
                              void* d_out, int out_size) {
    const float* x     = (const float*)d_in[0];
    const float* gamma = (const float*)d_in[1];
    const float* beta  = (const float*)d_in[2];
    const float* W1    = (const float*)d_in[3];
    const float* b1    = (const float*)d_in[4];
    const float* W2    = (const float*)d_in[5];
    const float* b2    = (const float*)d_in[6];
    const float* Wf    = (const float*)d_in[7];
    const float* bf    = (const float*)d_in[8];

    float* out = (float*)d_out;
    float* raw = out + (size_t)NROWS * DIM;

    cudaFuncSetAttribute(wchain,
                         cudaFuncAttributeMaxDynamicSharedMemorySize, GEMM_SMEM);
    cudaFuncSetAttribute(fused_final,
                         cudaFuncAttributeMaxDynamicSharedMemorySize, F_SMEM);

    prep<<<808, 256>>>(x, W2, Wf, b1, b2);
    wchain<<<352, 256, GEMM_SMEM>>>(x, Wf, bf);
    weff_k<<<72, 256>>>(W1, gamma, beta);
    fused_final<<<dim3(2, NROWS / 128), 128, F_SMEM>>>(x, raw, out);
}